// round 13
// baseline (speedup 1.0000x reference)
#include <cuda_runtime.h>
#include <cuda_bf16.h>
#include <math.h>
#include <stdint.h>

#define BB 4
#define NN 4096
#define KK 16
#define NB 32          // 2k neighbors per query
#define FULL 0xffffffffu

// ---------------- scratch (__device__ globals; no allocation allowed) -------
__device__ float g_feats[BB * NN * NB * 4];   // {rx,ry,rz,dist} per token, 8MB
// pre-folded, bf16-split, PRE-SWIZZLED weight tiles (64KB) + fp32 biases
__device__ uint4 g_wt4[4096];                 // bf16[32768]
__device__ float g_bias[256];                 // C0[0:64) C1[64:128) C2[128:256)

// bf16-unit offsets inside g_wt (prep writes)
#define WT_W0HI 0
#define WT_W0LO 4096
#define WT_W1HI 8192
#define WT_W1LO 12288
#define WT_W2HI 16384
#define WT_W2LO 24576
// byte offsets inside the smem weight block (mlp reads)
#define WB_W0HI 0
#define WB_W0LO 8192
#define WB_W1HI 16384
#define WB_W1LO 24576
#define WB_W2HI 32768
#define WB_W2LO 49152

// ---------------- small helpers --------------------------------------------
#define SWZ(b) ((b) ^ (((b) >> 3) & 0x70))

__device__ __forceinline__ uint32_t smem_u32(const void* p) {
    uint32_t a;
    asm("{ .reg .u64 t; cvta.to.shared.u64 t, %1; cvt.u32.u64 %0, t; }"
        : "=r"(a) : "l"(p));
    return a;
}
__device__ __forceinline__ void bsplit(float x, __nv_bfloat16& h, __nv_bfloat16& l) {
    h = __float2bfloat16(x);
    l = __float2bfloat16(x - __bfloat162float(h));
}
__device__ __forceinline__ uint32_t bpack(__nv_bfloat16 a, __nv_bfloat16 b) {
    return (uint32_t)__bfloat16_as_ushort(a) | ((uint32_t)__bfloat16_as_ushort(b) << 16);
}

// ---------------- mma.sync / ldmatrix wrappers (sm_80 features) -------------
__device__ __forceinline__ void ldsm_x4(uint32_t* r, uint32_t addr) {
    asm volatile("ldmatrix.sync.aligned.m8n8.x4.shared.b16 {%0,%1,%2,%3}, [%4];"
                 : "=r"(r[0]), "=r"(r[1]), "=r"(r[2]), "=r"(r[3]) : "r"(addr));
}
__device__ __forceinline__ void ldsm_x2(uint32_t* r, uint32_t addr) {
    asm volatile("ldmatrix.sync.aligned.m8n8.x2.shared.b16 {%0,%1}, [%2];"
                 : "=r"(r[0]), "=r"(r[1]) : "r"(addr));
}
__device__ __forceinline__ void mma_bf16(float* c, const uint32_t* a, const uint32_t* b) {
    asm volatile("mma.sync.aligned.m16n8k16.row.col.f32.bf16.bf16.f32 "
                 "{%0,%1,%2,%3}, {%4,%5,%6,%7}, {%8,%9}, {%0,%1,%2,%3};"
                 : "+f"(c[0]), "+f"(c[1]), "+f"(c[2]), "+f"(c[3])
                 : "r"(a[0]), "r"(a[1]), "r"(a[2]), "r"(a[3]),
                   "r"(b[0]), "r"(b[1]));
}

// ---------------- kNN: warp = 4 queries, warp-collective top-16 x4 ----------
// Tile read amortized over 4 queries (crossbar /4). Per step each lane
// evaluates 1 candidate against 4 queries; a combined any-ballot skips the
// per-query insert machinery on the (common) no-insert step.
__global__ __launch_bounds__(256) void knn_kernel(
    const float* __restrict__ p1, const float* __restrict__ p2)
{
    extern __shared__ float4 tile[];       // 4096 x {x,y,z,|r|^2}
    const int lane = threadIdx.x & 31;
    const int warp = threadIdx.x >> 5;     // 0..7
    const int b = blockIdx.y;
    const int set = blockIdx.z;

    const float* qb = p1 + b * 3 * NN;
    const float* rb = (set == 0 ? p1 : p2) + b * 3 * NN;

    for (int j = threadIdx.x; j < NN; j += 256) {
        float rx = rb[j], ry = rb[NN + j], rz = rb[2 * NN + j];
        tile[j] = make_float4(rx, ry, rz, rx * rx + ry * ry + rz * rz);
    }
    __syncthreads();

    const int q0 = blockIdx.x * 32 + warp * 4;
    float qx[4], qy[4], qz[4], qq[4];
#pragma unroll
    for (int i = 0; i < 4; i++) {                 // uniform broadcast loads
        qx[i] = qb[q0 + i];
        qy[i] = qb[NN + q0 + i];
        qz[i] = qb[2 * NN + q0 + i];
        qq[i] = qx[i] * qx[i] + qy[i] * qy[i] + qz[i] * qz[i];
    }

    float ld[4]; int li[4]; float th[4];

    // ---- init: bitonic sort of candidates 0..31, once per query ----
    {
        float4 c = tile[lane];
#pragma unroll
        for (int i = 0; i < 4; i++) {
            float dot = qx[i] * c.x + qy[i] * c.y + qz[i] * c.z;
            float d = fmaf(-2.0f, dot, qq[i]) + c.w;
            int idx = lane;
#pragma unroll
            for (int k = 2; k <= 32; k <<= 1) {
#pragma unroll
                for (int j = k >> 1; j > 0; j >>= 1) {
                    float od = __shfl_xor_sync(FULL, d, j);
                    int   oi = __shfl_xor_sync(FULL, idx, j);
                    bool up    = ((lane & k) == 0);
                    bool lower = ((lane & j) == 0);
                    bool lt = (od < d) || (od == d && oi < idx);
                    bool takeOther = (lt == (lower == up));
                    d   = takeOther ? od : d;
                    idx = takeOther ? oi : idx;
                }
            }
            ld[i] = d; li[i] = idx;
            th[i] = __shfl_sync(FULL, d, 15);
        }
    }

    // ---- stream remaining candidates ----
#pragma unroll 1
    for (int t = 1; t < NN / 32; t++) {
        const int j = t * 32 + lane;
        float4 c = tile[j];
        float d2[4]; bool p[4];
#pragma unroll
        for (int i = 0; i < 4; i++) {
            float dot = qx[i] * c.x + qy[i] * c.y + qz[i] * c.z;
            d2[i] = fmaf(-2.0f, dot, qq[i]) + c.w;
            p[i] = d2[i] < th[i];
        }
        if (__ballot_sync(FULL, p[0] | p[1] | p[2] | p[3])) {
#pragma unroll
            for (int i = 0; i < 4; i++) {
                unsigned mask = __ballot_sync(FULL, p[i]);
                if (mask) {
                    do {
                        int src = __ffs(mask) - 1;
                        mask &= mask - 1;
                        float xd = __shfl_sync(FULL, d2[i], src);
                        int   xi = __shfl_sync(FULL, j, src);
                        float pd = __shfl_up_sync(FULL, ld[i], 1);
                        int   pi = __shfl_up_sync(FULL, li[i], 1);
                        bool take  = (xd < ld[i]);
                        bool shift = (lane > 0) && (xd < pd);
                        ld[i] = take ? (shift ? pd : xd) : ld[i];
                        li[i] = take ? (shift ? pi : xi) : li[i];
                    } while (mask);
                    th[i] = __shfl_sync(FULL, ld[i], 15);
                }
            }
        }
    }

    if (lane < KK) {
#pragma unroll
        for (int i = 0; i < 4; i++) {
            float4 c = tile[li[i]];
            float rx = c.x - qx[i], ry = c.y - qy[i], rz = c.z - qz[i];
            float d2r = rx * rx + ry * ry + rz * rz;
            float dist = sqrtf(fmaxf(d2r, 1e-12f));
            ((float4*)g_feats)[((size_t)(b * NN + q0 + i)) * NB + set * KK + lane] =
                make_float4(rx, ry, rz, dist);
        }
    }
}

// ---------------- prep: fold BN, bf16-split, pre-swizzle weight tiles -------
__global__ void prep_kernel(
    const float* __restrict__ w0, const float* __restrict__ b0,
    const float* __restrict__ ga0, const float* __restrict__ be0,
    const float* __restrict__ mm0, const float* __restrict__ vv0,
    const float* __restrict__ w1, const float* __restrict__ b1,
    const float* __restrict__ ga1, const float* __restrict__ be1,
    const float* __restrict__ mm1, const float* __restrict__ vv1,
    const float* __restrict__ w2, const float* __restrict__ b2,
    const float* __restrict__ ga2, const float* __restrict__ be2,
    const float* __restrict__ mm2, const float* __restrict__ vv2)
{
    const int bid = blockIdx.x, tid = threadIdx.x;
    __nv_bfloat16* gw = reinterpret_cast<__nv_bfloat16*>(g_wt4);
    if (bid == 0) {
        for (int i = tid; i < 8192; i += 256) gw[i] = __float2bfloat16(0.0f);
        __syncthreads();
        {   // W0 [o<64][c<4] -> tile rows o (128B), cols c (K padded with zeros)
            int o = tid >> 2, c = tid & 3;
            float s = ga0[o] * rsqrtf(vv0[o] + 1e-3f);
            float wf = w0[o * 4 + c] * s;
            __nv_bfloat16 h, l; bsplit(wf, h, l);
            int pos = SWZ(o * 128 + c * 2) >> 1;
            gw[WT_W0HI + pos] = h;
            gw[WT_W0LO + pos] = l;
        }
        if (tid < 64) {
            float s = ga0[tid] * rsqrtf(vv0[tid] + 1e-3f);
            g_bias[tid] = (b0[tid] - mm0[tid]) * s + be0[tid];
        } else if (tid < 128) {
            int o = tid - 64;
            float s = ga1[o] * rsqrtf(vv1[o] + 1e-3f);
            g_bias[tid] = (b1[o] - mm1[o]) * s + be1[o];
        } else {
            int o = tid - 128;
            float s = ga2[o] * rsqrtf(vv2[o] + 1e-3f);
            g_bias[tid] = (b2[o] - mm2[o]) * s + be2[o];
        }
    } else if (bid <= 16) {
        int j = (bid - 1) * 256 + tid;       // < 4096
        int o = j >> 6, c = j & 63;
        float s = ga1[o] * rsqrtf(vv1[o] + 1e-3f);
        float wf = w1[o * 64 + c] * s;
        __nv_bfloat16 h, l; bsplit(wf, h, l);
        int pos = SWZ(o * 128 + c * 2) >> 1;
        gw[WT_W1HI + pos] = h;
        gw[WT_W1LO + pos] = l;
    } else {
        int j = (bid - 17) * 256 + tid;      // < 8192
        int o = j >> 6, c = j & 63;
        float s = ga2[o] * rsqrtf(vv2[o] + 1e-3f);
        float wf = w2[o * 64 + c] * s;
        __nv_bfloat16 h, l; bsplit(wf, h, l);
        int pos = SWZ(o * 128 + c * 2) >> 1;
        gw[WT_W2HI + pos] = h;
        gw[WT_W2LO + pos] = l;
    }
}

// ---------------- mma.sync MLP: 128 tokens/CTA, 3-term bf16-split -----------
// warp = one m16 token tile (8 warps). A act tiles [tok][128B] SW128 hi/lo;
// B weight tiles [ch][128B] SW128 (pre-swizzled). No __syncthreads in the
// main body: each warp's A rows are private; warp-sync mma orders in-place
// act updates (plus __syncwarp for cross-lane STS->LDSM visibility).
#define SM_AHI  0
#define SM_ALO  16384
#define SM_W    32768
#define SM_BIAS 98304
#define SM_GMAX 99328
#define SM_TOTAL (99840 + 1024)

// 64x64 GEMM tile: acc[8 ntiles][4], 3-term split, K=64 (4 k-steps)
__device__ __forceinline__ void gemm64(float (&acc)[8][4],
                                       uint32_t aHi, uint32_t aLo,
                                       uint32_t wHi, uint32_t wLo,
                                       int m0, int lane)
{
    uint32_t ah[16], al[16];
#pragma unroll
    for (int kk = 0; kk < 4; kk++) {
        uint32_t arow = (uint32_t)(m0 + (lane & 15)) * 128 + kk * 32 + ((lane >> 4) & 1) * 16;
        ldsm_x4(ah + kk * 4, aHi + SWZ(arow));
        ldsm_x4(al + kk * 4, aLo + SWZ(arow));
    }
#pragma unroll
    for (int nt = 0; nt < 8; nt++) {
#pragma unroll
        for (int kp = 0; kp < 2; kp++) {
            uint32_t boff = (uint32_t)(nt * 8 + (lane & 7)) * 128 + kp * 64 + (lane >> 3) * 16;
            uint32_t bh[4], bl[4];
            ldsm_x4(bh, wHi + SWZ(boff));
            ldsm_x4(bl, wLo + SWZ(boff));
            mma_bf16(acc[nt], ah + 8 * kp,     bh);
            mma_bf16(acc[nt], ah + 8 * kp,     bl);
            mma_bf16(acc[nt], al + 8 * kp,     bh);
            mma_bf16(acc[nt], ah + 8 * kp + 4, bh + 2);
            mma_bf16(acc[nt], ah + 8 * kp + 4, bl + 2);
            mma_bf16(acc[nt], al + 8 * kp + 4, bh + 2);
        }
    }
}

__global__ __launch_bounds__(256, 2) void mlp_mma_kernel(
    const float* __restrict__ p1, float* __restrict__ out)
{
    extern __shared__ char dsm[];
    const uint32_t base0 = smem_u32(dsm);
    const uint32_t base = (base0 + 1023u) & ~1023u;
    char* sm = dsm + (base - base0);

    const int tid = threadIdx.x;
    const int wid = tid >> 5;
    const int lane = tid & 31;
    const int m0 = wid * 16;

    // copy weights + biases into smem
    {
        uint4* dst = (uint4*)(sm + SM_W);
#pragma unroll 4
        for (int i = tid; i < 4096; i += 256) dst[i] = g_wt4[i];
        ((float*)(sm + SM_BIAS))[tid] = g_bias[tid];
    }

    // stage layer-0 A tiles: row = token (128B), k0-3 data, k4-15 zero
    const int tok0 = blockIdx.x * 128;
    if (tid < 128) {
        float4 f = ((const float4*)g_feats)[tok0 + tid];
        __nv_bfloat16 h0, l0, h1, l1, h2, l2, h3, l3;
        bsplit(f.x, h0, l0); bsplit(f.y, h1, l1);
        bsplit(f.z, h2, l2); bsplit(f.w, h3, l3);
        uint32_t ro = (uint32_t)tid * 128;
        *(uint4*)(sm + SM_AHI + SWZ(ro))      = make_uint4(bpack(h0, h1), bpack(h2, h3), 0u, 0u);
        *(uint4*)(sm + SM_AHI + SWZ(ro + 16)) = make_uint4(0u, 0u, 0u, 0u);
        *(uint4*)(sm + SM_ALO + SWZ(ro))      = make_uint4(bpack(l0, l1), bpack(l2, l3), 0u, 0u);
        *(uint4*)(sm + SM_ALO + SWZ(ro + 16)) = make_uint4(0u, 0u, 0u, 0u);
    }
    __syncthreads();

    const uint32_t aHi = base + SM_AHI;
    const uint32_t aLo = base + SM_ALO;
    const uint32_t wB  = base + SM_W;
    const float* sb = (const float*)(sm + SM_BIAS);

    float acc[8][4];

    // ---------------- layer 0: K=16 (single k-step) ----------------
    {
        uint32_t arow = (uint32_t)(m0 + (lane & 15)) * 128 + ((lane >> 4) & 1) * 16;
        uint32_t ah[4], al[4];
        ldsm_x4(ah, aHi + SWZ(arow));
        ldsm_x4(al, aLo + SWZ(arow));
#pragma unroll
        for (int nt = 0; nt < 8; nt++) {
#pragma unroll
            for (int i = 0; i < 4; i++) acc[nt][i] = 0.0f;
            uint32_t boff = (uint32_t)(nt * 8 + (lane & 7)) * 128 + ((lane >> 3) & 1) * 16;
            uint32_t bh[2], bl[2];
            ldsm_x2(bh, wB + WB_W0HI + SWZ(boff));
            ldsm_x2(bl, wB + WB_W0LO + SWZ(boff));
            mma_bf16(acc[nt], ah, bh);
            mma_bf16(acc[nt], ah, bl);
            mma_bf16(acc[nt], al, bh);
        }
    }
    // epilogue: bias + relu + split -> act (in place; warp-private rows)
#pragma unroll
    for (int nt = 0; nt < 8; nt++) {
        float2 b2 = *(const float2*)(sb + nt * 8 + (lane & 3) * 2);
        float v0 = fmaxf(acc[nt][0] + b2.x, 0.f);
        float v1 = fmaxf(acc[nt][1] + b2.y, 0.f);
        float v2 = fmaxf(acc[nt][2] + b2.x, 0.f);
        float v3 = fmaxf(acc[nt][3] + b2.y, 0.f);
        __nv_bfloat16 h0, l0, h1, l1, h2, l2, h3, l3;
        bsplit(v0, h0, l0); bsplit(v1, h1, l1);
        bsplit(v2, h2, l2); bsplit(v3, h3, l3);
        uint32_t r0b = (uint32_t)(m0 + (lane >> 2)) * 128 + nt * 16 + (lane & 3) * 4;
        uint32_t r1b = r0b + 8 * 128;
        *(uint32_t*)(sm + SM_AHI + SWZ(r0b)) = bpack(h0, h1);
        *(uint32_t*)(sm + SM_ALO + SWZ(r0b)) = bpack(l0, l1);
        *(uint32_t*)(sm + SM_AHI + SWZ(r1b)) = bpack(h2, h3);
        *(uint32_t*)(sm + SM_ALO + SWZ(r1b)) = bpack(l2, l3);
    }
    __syncwarp();

    // ---------------- layer 1: 64 -> 64 ----------------
#pragma unroll
    for (int nt = 0; nt < 8; nt++)
#pragma unroll
        for (int i = 0; i < 4; i++) acc[nt][i] = 0.0f;
    gemm64(acc, aHi, aLo, wB + WB_W1HI, wB + WB_W1LO, m0, lane);
#pragma unroll
    for (int nt = 0; nt < 8; nt++) {
        float2 b2 = *(const float2*)(sb + 64 + nt * 8 + (lane & 3) * 2);
        float v0 = fmaxf(acc[nt][0] + b2.x, 0.f);
        float v1 = fmaxf(acc[nt][1] + b2.y, 0.f);
        float v2 = fmaxf(acc[nt][2] + b2.x, 0.f);
        float v3 = fmaxf(acc[nt][3] + b2.y, 0.f);
        __nv_bfloat16 h0, l0, h1, l1, h2, l2, h3, l3;
        bsplit(v0, h0, l0); bsplit(v1, h1, l1);
        bsplit(v2, h2, l2); bsplit(v3, h3, l3);
        uint32_t r0b = (uint32_t)(m0 + (lane >> 2)) * 128 + nt * 16 + (lane & 3) * 4;
        uint32_t r1b = r0b + 8 * 128;
        *(uint32_t*)(sm + SM_AHI + SWZ(r0b)) = bpack(h0, h1);
        *(uint32_t*)(sm + SM_ALO + SWZ(r0b)) = bpack(l0, l1);
        *(uint32_t*)(sm + SM_AHI + SWZ(r1b)) = bpack(h2, h3);
        *(uint32_t*)(sm + SM_ALO + SWZ(r1b)) = bpack(l2, l3);
    }
    __syncwarp();

    // ---------------- layer 2: 64 -> 128 (two N=64 halves), channel max ----
    float tmA = 0.0f, tmB = 0.0f;   // relu floor = 0
#pragma unroll 1
    for (int h = 0; h < 2; h++) {
#pragma unroll
        for (int nt = 0; nt < 8; nt++)
#pragma unroll
            for (int i = 0; i < 4; i++) acc[nt][i] = 0.0f;
        gemm64(acc, aHi, aLo, wB + WB_W2HI + h * 8192, wB + WB_W2LO + h * 8192, m0, lane);
#pragma unroll
        for (int nt = 0; nt < 8; nt++) {
            float2 b2 = *(const float2*)(sb + 128 + h * 64 + nt * 8 + (lane & 3) * 2);
            tmA = fmaxf(tmA, fmaxf(acc[nt][0] + b2.x, acc[nt][1] + b2.y));
            tmB = fmaxf(tmB, fmaxf(acc[nt][2] + b2.x, acc[nt][3] + b2.y));
        }
    }
    // reduce across the 4 lanes sharing each token row
    tmA = fmaxf(tmA, __shfl_xor_sync(FULL, tmA, 1));
    tmA = fmaxf(tmA, __shfl_xor_sync(FULL, tmA, 2));
    tmB = fmaxf(tmB, __shfl_xor_sync(FULL, tmB, 1));
    tmB = fmaxf(tmB, __shfl_xor_sync(FULL, tmB, 2));
    {
        float* gm = (float*)(sm + SM_GMAX);
        if ((lane & 3) == 0) {
            gm[m0 + (lane >> 2)]     = tmA;
            gm[m0 + 8 + (lane >> 2)] = tmB;
        }
    }
    __syncthreads();

    // ---------------- softmax (warp = query) + weighted sum ----------------
    if (tid < 128) {
        const float* gm = (const float*)(sm + SM_GMAX);
        float gmax = gm[tid];

        float m = gmax;
#pragma unroll
        for (int off = 16; off; off >>= 1) m = fmaxf(m, __shfl_xor_sync(FULL, m, off));
        float e = __expf(gmax - m);
        float ssum = e;
#pragma unroll
        for (int off = 16; off; off >>= 1) ssum += __shfl_xor_sync(FULL, ssum, off);
        float w = e / ssum;

        float4 f = ((const float4*)g_feats)[tok0 + tid];
        float wx = w * f.x, wy = w * f.y, wz = w * f.z;
#pragma unroll
        for (int off = 16; off; off >>= 1) {
            wx += __shfl_xor_sync(FULL, wx, off);
            wy += __shfl_xor_sync(FULL, wy, off);
            wz += __shfl_xor_sync(FULL, wz, off);
        }
        if (lane == 0) {
            const int wg = blockIdx.x * 4 + (tid >> 5);   // = b*NN + n
            const int b = wg >> 12;
            const int n = wg & (NN - 1);
            const float* qb = p1 + b * 3 * NN;
            out[b * 3 * NN + n]          = qb[n]          + wx;
            out[b * 3 * NN + NN + n]     = qb[NN + n]     + wy;
            out[b * 3 * NN + 2 * NN + n] = qb[2 * NN + n] + wz;
        }
    }
}

// ---------------- launch ---------------------------------------------------
extern "C" void kernel_launch(void* const* d_in, const int* in_sizes, int n_in,
                              void* d_out, int out_size)
{
    const float* p1 = (const float*)d_in[0];
    const float* p2 = (const float*)d_in[1];
    // d_in[2] = k (fixed at 16 for this shape)
    const float* w0 = (const float*)d_in[3];
    const float* b0 = (const float*)d_in[4];
    const float* g0 = (const float*)d_in[5];
    const float* e0 = (const float*)d_in[6];
    const float* m0 = (const float*)d_in[7];
    const float* v0 = (const float*)d_in[8];
    const float* w1 = (const float*)d_in[9];
    const float* b1 = (const float*)d_in[10];
    const float* g1 = (const float*)d_in[11];
    const float* e1 = (const float*)d_in[12];
    const float* m1 = (const float*)d_in[13];
    const float* v1 = (const float*)d_in[14];
    const float* w2 = (const float*)d_in[15];
    const float* b2 = (const float*)d_in[16];
    const float* g2 = (const float*)d_in[17];
    const float* e2 = (const float*)d_in[18];
    const float* m2 = (const float*)d_in[19];
    const float* v2 = (const float*)d_in[20];

    cudaFuncSetAttribute(knn_kernel, cudaFuncAttributeMaxDynamicSharedMemorySize, NN * 16);
    cudaFuncSetAttribute(mlp_mma_kernel, cudaFuncAttributeMaxDynamicSharedMemorySize, SM_TOTAL);

    prep_kernel<<<49, 256>>>(w0, b0, g0, e0, m0, v0,
                             w1, b1, g1, e1, m1, v1,
                             w2, b2, g2, e2, m2, v2);

    knn_kernel<<<dim3(NN / 32, BB, 2), 256, NN * 16>>>(p1, p2);

    mlp_mma_kernel<<<BB * NN * NB / 128, 256, SM_TOTAL>>>(p1, (float*)d_out);
}

// round 14
// speedup vs baseline: 1.1464x; 1.1464x over previous
#include <cuda_runtime.h>
#include <cuda_bf16.h>
#include <math.h>
#include <stdint.h>

#define BB 4
#define NN 4096
#define KK 16
#define NB 32          // 2k neighbors per query
#define FULL 0xffffffffu

// ---------------- scratch (__device__ globals; no allocation allowed) -------
__device__ float g_feats[BB * NN * NB * 4];   // {rx,ry,rz,dist} per token, 8MB
// pre-folded, bf16-split, PRE-SWIZZLED weight tiles (64KB) + fp32 biases
__device__ uint4 g_wt4[4096];                 // bf16[32768]
__device__ float g_bias[256];                 // C0[0:64) C1[64:128) C2[128:256)

// bf16-unit offsets inside g_wt (prep writes)
#define WT_W0HI 0
#define WT_W0LO 4096
#define WT_W1HI 8192
#define WT_W1LO 12288
#define WT_W2HI 16384
#define WT_W2LO 24576
// byte offsets inside the smem weight block (mlp reads)
#define WB_W0HI 0
#define WB_W0LO 8192
#define WB_W1HI 16384
#define WB_W1LO 24576
#define WB_W2HI 32768
#define WB_W2LO 49152

// ---------------- small helpers --------------------------------------------
#define SWZ(b) ((b) ^ (((b) >> 3) & 0x70))

__device__ __forceinline__ uint32_t smem_u32(const void* p) {
    uint32_t a;
    asm("{ .reg .u64 t; cvta.to.shared.u64 t, %1; cvt.u32.u64 %0, t; }"
        : "=r"(a) : "l"(p));
    return a;
}
__device__ __forceinline__ void bsplit(float x, __nv_bfloat16& h, __nv_bfloat16& l) {
    h = __float2bfloat16(x);
    l = __float2bfloat16(x - __bfloat162float(h));
}
__device__ __forceinline__ uint32_t bpack(__nv_bfloat16 a, __nv_bfloat16 b) {
    return (uint32_t)__bfloat16_as_ushort(a) | ((uint32_t)__bfloat16_as_ushort(b) << 16);
}

// ---------------- mma.sync / ldmatrix wrappers (sm_80 features) -------------
__device__ __forceinline__ void ldsm_x4(uint32_t* r, uint32_t addr) {
    asm volatile("ldmatrix.sync.aligned.m8n8.x4.shared.b16 {%0,%1,%2,%3}, [%4];"
                 : "=r"(r[0]), "=r"(r[1]), "=r"(r[2]), "=r"(r[3]) : "r"(addr));
}
__device__ __forceinline__ void ldsm_x2(uint32_t* r, uint32_t addr) {
    asm volatile("ldmatrix.sync.aligned.m8n8.x2.shared.b16 {%0,%1}, [%2];"
                 : "=r"(r[0]), "=r"(r[1]) : "r"(addr));
}
__device__ __forceinline__ void mma_bf16(float* c, const uint32_t* a, const uint32_t* b) {
    asm volatile("mma.sync.aligned.m16n8k16.row.col.f32.bf16.bf16.f32 "
                 "{%0,%1,%2,%3}, {%4,%5,%6,%7}, {%8,%9}, {%0,%1,%2,%3};"
                 : "+f"(c[0]), "+f"(c[1]), "+f"(c[2]), "+f"(c[3])
                 : "r"(a[0]), "r"(a[1]), "r"(a[2]), "r"(a[3]),
                   "r"(b[0]), "r"(b[1]));
}

// ---------------- kNN: warp = 2 queries, warp-collective top-16 x2 ----------
// 512 threads = 16 warps = 32 queries/block. Tile LDS per step serves 2
// queries (wavefront cost /2). Two unconditional per-query ballots per step
// (no or-ballot fast-path: at ~87% any-hit rate it only added cost in R13).
// Insert machinery identical to the proven single-query version.
__global__ __launch_bounds__(512) void knn_kernel(
    const float* __restrict__ p1, const float* __restrict__ p2)
{
    extern __shared__ float4 tile[];       // 4096 x {x,y,z,|r|^2}
    const int lane = threadIdx.x & 31;
    const int warp = threadIdx.x >> 5;     // 0..15
    const int b = blockIdx.y;
    const int set = blockIdx.z;

    const float* qb = p1 + b * 3 * NN;
    const float* rb = (set == 0 ? p1 : p2) + b * 3 * NN;

    for (int j = threadIdx.x; j < NN; j += 512) {
        float rx = rb[j], ry = rb[NN + j], rz = rb[2 * NN + j];
        tile[j] = make_float4(rx, ry, rz, rx * rx + ry * ry + rz * rz);
    }
    __syncthreads();

    const int q0 = blockIdx.x * 32 + warp * 2;
    float qx0 = qb[q0],     qy0 = qb[NN + q0],     qz0 = qb[2 * NN + q0];
    float qx1 = qb[q0 + 1], qy1 = qb[NN + q0 + 1], qz1 = qb[2 * NN + q0 + 1];
    const float qq0 = qx0 * qx0 + qy0 * qy0 + qz0 * qz0;
    const float qq1 = qx1 * qx1 + qy1 * qy1 + qz1 * qz1;

    float ld0, ld1; int li0, li1; float th0, th1;

    // ---- init: bitonic sort of candidates 0..31, once per query ----
    {
        float4 c = tile[lane];
#pragma unroll
        for (int i = 0; i < 2; i++) {
            float dot = (i == 0) ? (qx0 * c.x + qy0 * c.y + qz0 * c.z)
                                 : (qx1 * c.x + qy1 * c.y + qz1 * c.z);
            float d = fmaf(-2.0f, dot, (i == 0) ? qq0 : qq1) + c.w;
            int idx = lane;
#pragma unroll
            for (int k = 2; k <= 32; k <<= 1) {
#pragma unroll
                for (int j = k >> 1; j > 0; j >>= 1) {
                    float od = __shfl_xor_sync(FULL, d, j);
                    int   oi = __shfl_xor_sync(FULL, idx, j);
                    bool up    = ((lane & k) == 0);
                    bool lower = ((lane & j) == 0);
                    bool lt = (od < d) || (od == d && oi < idx);
                    bool takeOther = (lt == (lower == up));
                    d   = takeOther ? od : d;
                    idx = takeOther ? oi : idx;
                }
            }
            if (i == 0) { ld0 = d; li0 = idx; th0 = __shfl_sync(FULL, d, 15); }
            else        { ld1 = d; li1 = idx; th1 = __shfl_sync(FULL, d, 15); }
        }
    }

    // ---- stream remaining candidates (2 queries per tile read) ----
#pragma unroll 1
    for (int t = 1; t < NN / 32; t++) {
        const int j = t * 32 + lane;
        float4 c = tile[j];
        float dot0 = qx0 * c.x + qy0 * c.y + qz0 * c.z;
        float dot1 = qx1 * c.x + qy1 * c.y + qz1 * c.z;
        float d20 = fmaf(-2.0f, dot0, qq0) + c.w;
        float d21 = fmaf(-2.0f, dot1, qq1) + c.w;

        unsigned mask = __ballot_sync(FULL, d20 < th0);
        if (mask) {
            do {
                int src = __ffs(mask) - 1;
                mask &= mask - 1;
                float xd = __shfl_sync(FULL, d20, src);
                int   xi = __shfl_sync(FULL, j, src);
                float pd = __shfl_up_sync(FULL, ld0, 1);
                int   pi = __shfl_up_sync(FULL, li0, 1);
                bool take  = (xd < ld0);
                bool shift = (lane > 0) && (xd < pd);
                ld0 = take ? (shift ? pd : xd) : ld0;
                li0 = take ? (shift ? pi : xi) : li0;
            } while (mask);
            th0 = __shfl_sync(FULL, ld0, 15);
        }
        mask = __ballot_sync(FULL, d21 < th1);
        if (mask) {
            do {
                int src = __ffs(mask) - 1;
                mask &= mask - 1;
                float xd = __shfl_sync(FULL, d21, src);
                int   xi = __shfl_sync(FULL, j, src);
                float pd = __shfl_up_sync(FULL, ld1, 1);
                int   pi = __shfl_up_sync(FULL, li1, 1);
                bool take  = (xd < ld1);
                bool shift = (lane > 0) && (xd < pd);
                ld1 = take ? (shift ? pd : xd) : ld1;
                li1 = take ? (shift ? pi : xi) : li1;
            } while (mask);
            th1 = __shfl_sync(FULL, ld1, 15);
        }
    }

    if (lane < KK) {
        {
            float4 c = tile[li0];
            float rx = c.x - qx0, ry = c.y - qy0, rz = c.z - qz0;
            float d2r = rx * rx + ry * ry + rz * rz;
            float dist = sqrtf(fmaxf(d2r, 1e-12f));
            ((float4*)g_feats)[((size_t)(b * NN + q0)) * NB + set * KK + lane] =
                make_float4(rx, ry, rz, dist);
        }
        {
            float4 c = tile[li1];
            float rx = c.x - qx1, ry = c.y - qy1, rz = c.z - qz1;
            float d2r = rx * rx + ry * ry + rz * rz;
            float dist = sqrtf(fmaxf(d2r, 1e-12f));
            ((float4*)g_feats)[((size_t)(b * NN + q0 + 1)) * NB + set * KK + lane] =
                make_float4(rx, ry, rz, dist);
        }
    }
}

// ---------------- prep: fold BN, bf16-split, pre-swizzle weight tiles -------
__global__ void prep_kernel(
    const float* __restrict__ w0, const float* __restrict__ b0,
    const float* __restrict__ ga0, const float* __restrict__ be0,
    const float* __restrict__ mm0, const float* __restrict__ vv0,
    const float* __restrict__ w1, const float* __restrict__ b1,
    const float* __restrict__ ga1, const float* __restrict__ be1,
    const float* __restrict__ mm1, const float* __restrict__ vv1,
    const float* __restrict__ w2, const float* __restrict__ b2,
    const float* __restrict__ ga2, const float* __restrict__ be2,
    const float* __restrict__ mm2, const float* __restrict__ vv2)
{
    const int bid = blockIdx.x, tid = threadIdx.x;
    __nv_bfloat16* gw = reinterpret_cast<__nv_bfloat16*>(g_wt4);
    if (bid == 0) {
        for (int i = tid; i < 8192; i += 256) gw[i] = __float2bfloat16(0.0f);
        __syncthreads();
        {   // W0 [o<64][c<4] -> tile rows o (128B), cols c (K padded with zeros)
            int o = tid >> 2, c = tid & 3;
            float s = ga0[o] * rsqrtf(vv0[o] + 1e-3f);
            float wf = w0[o * 4 + c] * s;
            __nv_bfloat16 h, l; bsplit(wf, h, l);
            int pos = SWZ(o * 128 + c * 2) >> 1;
            gw[WT_W0HI + pos] = h;
            gw[WT_W0LO + pos] = l;
        }
        if (tid < 64) {
            float s = ga0[tid] * rsqrtf(vv0[tid] + 1e-3f);
            g_bias[tid] = (b0[tid] - mm0[tid]) * s + be0[tid];
        } else if (tid < 128) {
            int o = tid - 64;
            float s = ga1[o] * rsqrtf(vv1[o] + 1e-3f);
            g_bias[tid] = (b1[o] - mm1[o]) * s + be1[o];
        } else {
            int o = tid - 128;
            float s = ga2[o] * rsqrtf(vv2[o] + 1e-3f);
            g_bias[tid] = (b2[o] - mm2[o]) * s + be2[o];
        }
    } else if (bid <= 16) {
        int j = (bid - 1) * 256 + tid;       // < 4096
        int o = j >> 6, c = j & 63;
        float s = ga1[o] * rsqrtf(vv1[o] + 1e-3f);
        float wf = w1[o * 64 + c] * s;
        __nv_bfloat16 h, l; bsplit(wf, h, l);
        int pos = SWZ(o * 128 + c * 2) >> 1;
        gw[WT_W1HI + pos] = h;
        gw[WT_W1LO + pos] = l;
    } else {
        int j = (bid - 17) * 256 + tid;      // < 8192
        int o = j >> 6, c = j & 63;
        float s = ga2[o] * rsqrtf(vv2[o] + 1e-3f);
        float wf = w2[o * 64 + c] * s;
        __nv_bfloat16 h, l; bsplit(wf, h, l);
        int pos = SWZ(o * 128 + c * 2) >> 1;
        gw[WT_W2HI + pos] = h;
        gw[WT_W2LO + pos] = l;
    }
}

// ---------------- mma.sync MLP: 128 tokens/CTA, 3-term bf16-split -----------
// warp = one m16 token tile (8 warps). A act tiles [tok][128B] SW128 hi/lo;
// B weight tiles [ch][128B] SW128 (pre-swizzled). No __syncthreads in the
// main body: each warp's A rows are private; warp-sync mma orders in-place
// act updates (plus __syncwarp for cross-lane STS->LDSM visibility).
#define SM_AHI  0
#define SM_ALO  16384
#define SM_W    32768
#define SM_BIAS 98304
#define SM_GMAX 99328
#define SM_TOTAL (99840 + 1024)

// 64x64 GEMM tile: acc[8 ntiles][4], 3-term split, K=64 (4 k-steps)
__device__ __forceinline__ void gemm64(float (&acc)[8][4],
                                       uint32_t aHi, uint32_t aLo,
                                       uint32_t wHi, uint32_t wLo,
                                       int m0, int lane)
{
    uint32_t ah[16], al[16];
#pragma unroll
    for (int kk = 0; kk < 4; kk++) {
        uint32_t arow = (uint32_t)(m0 + (lane & 15)) * 128 + kk * 32 + ((lane >> 4) & 1) * 16;
        ldsm_x4(ah + kk * 4, aHi + SWZ(arow));
        ldsm_x4(al + kk * 4, aLo + SWZ(arow));
    }
#pragma unroll
    for (int nt = 0; nt < 8; nt++) {
#pragma unroll
        for (int kp = 0; kp < 2; kp++) {
            uint32_t boff = (uint32_t)(nt * 8 + (lane & 7)) * 128 + kp * 64 + (lane >> 3) * 16;
            uint32_t bh[4], bl[4];
            ldsm_x4(bh, wHi + SWZ(boff));
            ldsm_x4(bl, wLo + SWZ(boff));
            mma_bf16(acc[nt], ah + 8 * kp,     bh);
            mma_bf16(acc[nt], ah + 8 * kp,     bl);
            mma_bf16(acc[nt], al + 8 * kp,     bh);
            mma_bf16(acc[nt], ah + 8 * kp + 4, bh + 2);
            mma_bf16(acc[nt], ah + 8 * kp + 4, bl + 2);
            mma_bf16(acc[nt], al + 8 * kp + 4, bh + 2);
        }
    }
}

__global__ __launch_bounds__(256, 2) void mlp_mma_kernel(
    const float* __restrict__ p1, float* __restrict__ out)
{
    extern __shared__ char dsm[];
    const uint32_t base0 = smem_u32(dsm);
    const uint32_t base = (base0 + 1023u) & ~1023u;
    char* sm = dsm + (base - base0);

    const int tid = threadIdx.x;
    const int wid = tid >> 5;
    const int lane = tid & 31;
    const int m0 = wid * 16;

    // copy weights + biases into smem
    {
        uint4* dst = (uint4*)(sm + SM_W);
#pragma unroll 4
        for (int i = tid; i < 4096; i += 256) dst[i] = g_wt4[i];
        ((float*)(sm + SM_BIAS))[tid] = g_bias[tid];
    }

    // stage layer-0 A tiles: row = token (128B), k0-3 data, k4-15 zero
    const int tok0 = blockIdx.x * 128;
    if (tid < 128) {
        float4 f = ((const float4*)g_feats)[tok0 + tid];
        __nv_bfloat16 h0, l0, h1, l1, h2, l2, h3, l3;
        bsplit(f.x, h0, l0); bsplit(f.y, h1, l1);
        bsplit(f.z, h2, l2); bsplit(f.w, h3, l3);
        uint32_t ro = (uint32_t)tid * 128;
        *(uint4*)(sm + SM_AHI + SWZ(ro))      = make_uint4(bpack(h0, h1), bpack(h2, h3), 0u, 0u);
        *(uint4*)(sm + SM_AHI + SWZ(ro + 16)) = make_uint4(0u, 0u, 0u, 0u);
        *(uint4*)(sm + SM_ALO + SWZ(ro))      = make_uint4(bpack(l0, l1), bpack(l2, l3), 0u, 0u);
        *(uint4*)(sm + SM_ALO + SWZ(ro + 16)) = make_uint4(0u, 0u, 0u, 0u);
    }
    __syncthreads();

    const uint32_t aHi = base + SM_AHI;
    const uint32_t aLo = base + SM_ALO;
    const uint32_t wB  = base + SM_W;
    const float* sb = (const float*)(sm + SM_BIAS);

    float acc[8][4];

    // ---------------- layer 0: K=16 (single k-step) ----------------
    {
        uint32_t arow = (uint32_t)(m0 + (lane & 15)) * 128 + ((lane >> 4) & 1) * 16;
        uint32_t ah[4], al[4];
        ldsm_x4(ah, aHi + SWZ(arow));
        ldsm_x4(al, aLo + SWZ(arow));
#pragma unroll
        for (int nt = 0; nt < 8; nt++) {
#pragma unroll
            for (int i = 0; i < 4; i++) acc[nt][i] = 0.0f;
            uint32_t boff = (uint32_t)(nt * 8 + (lane & 7)) * 128 + ((lane >> 3) & 1) * 16;
            uint32_t bh[2], bl[2];
            ldsm_x2(bh, wB + WB_W0HI + SWZ(boff));
            ldsm_x2(bl, wB + WB_W0LO + SWZ(boff));
            mma_bf16(acc[nt], ah, bh);
            mma_bf16(acc[nt], ah, bl);
            mma_bf16(acc[nt], al, bh);
        }
    }
    // epilogue: bias + relu + split -> act (in place; warp-private rows)
#pragma unroll
    for (int nt = 0; nt < 8; nt++) {
        float2 b2 = *(const float2*)(sb + nt * 8 + (lane & 3) * 2);
        float v0 = fmaxf(acc[nt][0] + b2.x, 0.f);
        float v1 = fmaxf(acc[nt][1] + b2.y, 0.f);
        float v2 = fmaxf(acc[nt][2] + b2.x, 0.f);
        float v3 = fmaxf(acc[nt][3] + b2.y, 0.f);
        __nv_bfloat16 h0, l0, h1, l1, h2, l2, h3, l3;
        bsplit(v0, h0, l0); bsplit(v1, h1, l1);
        bsplit(v2, h2, l2); bsplit(v3, h3, l3);
        uint32_t r0b = (uint32_t)(m0 + (lane >> 2)) * 128 + nt * 16 + (lane & 3) * 4;
        uint32_t r1b = r0b + 8 * 128;
        *(uint32_t*)(sm + SM_AHI + SWZ(r0b)) = bpack(h0, h1);
        *(uint32_t*)(sm + SM_ALO + SWZ(r0b)) = bpack(l0, l1);
        *(uint32_t*)(sm + SM_AHI + SWZ(r1b)) = bpack(h2, h3);
        *(uint32_t*)(sm + SM_ALO + SWZ(r1b)) = bpack(l2, l3);
    }
    __syncwarp();

    // ---------------- layer 1: 64 -> 64 ----------------
#pragma unroll
    for (int nt = 0; nt < 8; nt++)
#pragma unroll
        for (int i = 0; i < 4; i++) acc[nt][i] = 0.0f;
    gemm64(acc, aHi, aLo, wB + WB_W1HI, wB + WB_W1LO, m0, lane);
#pragma unroll
    for (int nt = 0; nt < 8; nt++) {
        float2 b2 = *(const float2*)(sb + 64 + nt * 8 + (lane & 3) * 2);
        float v0 = fmaxf(acc[nt][0] + b2.x, 0.f);
        float v1 = fmaxf(acc[nt][1] + b2.y, 0.f);
        float v2 = fmaxf(acc[nt][2] + b2.x, 0.f);
        float v3 = fmaxf(acc[nt][3] + b2.y, 0.f);
        __nv_bfloat16 h0, l0, h1, l1, h2, l2, h3, l3;
        bsplit(v0, h0, l0); bsplit(v1, h1, l1);
        bsplit(v2, h2, l2); bsplit(v3, h3, l3);
        uint32_t r0b = (uint32_t)(m0 + (lane >> 2)) * 128 + nt * 16 + (lane & 3) * 4;
        uint32_t r1b = r0b + 8 * 128;
        *(uint32_t*)(sm + SM_AHI + SWZ(r0b)) = bpack(h0, h1);
        *(uint32_t*)(sm + SM_ALO + SWZ(r0b)) = bpack(l0, l1);
        *(uint32_t*)(sm + SM_AHI + SWZ(r1b)) = bpack(h2, h3);
        *(uint32_t*)(sm + SM_ALO + SWZ(r1b)) = bpack(l2, l3);
    }
    __syncwarp();

    // ---------------- layer 2: 64 -> 128 (two N=64 halves), channel max ----
    float tmA = 0.0f, tmB = 0.0f;   // relu floor = 0
#pragma unroll 1
    for (int h = 0; h < 2; h++) {
#pragma unroll
        for (int nt = 0; nt < 8; nt++)
#pragma unroll
            for (int i = 0; i < 4; i++) acc[nt][i] = 0.0f;
        gemm64(acc, aHi, aLo, wB + WB_W2HI + h * 8192, wB + WB_W2LO + h * 8192, m0, lane);
#pragma unroll
        for (int nt = 0; nt < 8; nt++) {
            float2 b2 = *(const float2*)(sb + 128 + h * 64 + nt * 8 + (lane & 3) * 2);
            tmA = fmaxf(tmA, fmaxf(acc[nt][0] + b2.x, acc[nt][1] + b2.y));
            tmB = fmaxf(tmB, fmaxf(acc[nt][2] + b2.x, acc[nt][3] + b2.y));
        }
    }
    // reduce across the 4 lanes sharing each token row
    tmA = fmaxf(tmA, __shfl_xor_sync(FULL, tmA, 1));
    tmA = fmaxf(tmA, __shfl_xor_sync(FULL, tmA, 2));
    tmB = fmaxf(tmB, __shfl_xor_sync(FULL, tmB, 1));
    tmB = fmaxf(tmB, __shfl_xor_sync(FULL, tmB, 2));
    {
        float* gm = (float*)(sm + SM_GMAX);
        if ((lane & 3) == 0) {
            gm[m0 + (lane >> 2)]     = tmA;
            gm[m0 + 8 + (lane >> 2)] = tmB;
        }
    }
    __syncthreads();

    // ---------------- softmax (warp = query) + weighted sum ----------------
    if (tid < 128) {
        const float* gm = (const float*)(sm + SM_GMAX);
        float gmax = gm[tid];

        float m = gmax;
#pragma unroll
        for (int off = 16; off; off >>= 1) m = fmaxf(m, __shfl_xor_sync(FULL, m, off));
        float e = __expf(gmax - m);
        float ssum = e;
#pragma unroll
        for (int off = 16; off; off >>= 1) ssum += __shfl_xor_sync(FULL, ssum, off);
        float w = e / ssum;

        float4 f = ((const float4*)g_feats)[tok0 + tid];
        float wx = w * f.x, wy = w * f.y, wz = w * f.z;
#pragma unroll
        for (int off = 16; off; off >>= 1) {
            wx += __shfl_xor_sync(FULL, wx, off);
            wy += __shfl_xor_sync(FULL, wy, off);
            wz += __shfl_xor_sync(FULL, wz, off);
        }
        if (lane == 0) {
            const int wg = blockIdx.x * 4 + (tid >> 5);   // = b*NN + n
            const int b = wg >> 12;
            const int n = wg & (NN - 1);
            const float* qb = p1 + b * 3 * NN;
            out[b * 3 * NN + n]          = qb[n]          + wx;
            out[b * 3 * NN + NN + n]     = qb[NN + n]     + wy;
            out[b * 3 * NN + 2 * NN + n] = qb[2 * NN + n] + wz;
        }
    }
}

// ---------------- launch ---------------------------------------------------
extern "C" void kernel_launch(void* const* d_in, const int* in_sizes, int n_in,
                              void* d_out, int out_size)
{
    const float* p1 = (const float*)d_in[0];
    const float* p2 = (const float*)d_in[1];
    // d_in[2] = k (fixed at 16 for this shape)
    const float* w0 = (const float*)d_in[3];
    const float* b0 = (const float*)d_in[4];
    const float* g0 = (const float*)d_in[5];
    const float* e0 = (const float*)d_in[6];
    const float* m0 = (const float*)d_in[7];
    const float* v0 = (const float*)d_in[8];
    const float* w1 = (const float*)d_in[9];
    const float* b1 = (const float*)d_in[10];
    const float* g1 = (const float*)d_in[11];
    const float* e1 = (const float*)d_in[12];
    const float* m1 = (const float*)d_in[13];
    const float* v1 = (const float*)d_in[14];
    const float* w2 = (const float*)d_in[15];
    const float* b2 = (const float*)d_in[16];
    const float* g2 = (const float*)d_in[17];
    const float* e2 = (const float*)d_in[18];
    const float* m2 = (const float*)d_in[19];
    const float* v2 = (const float*)d_in[20];

    cudaFuncSetAttribute(knn_kernel, cudaFuncAttributeMaxDynamicSharedMemorySize, NN * 16);
    cudaFuncSetAttribute(mlp_mma_kernel, cudaFuncAttributeMaxDynamicSharedMemorySize, SM_TOTAL);

    prep_kernel<<<49, 256>>>(w0, b0, g0, e0, m0, v0,
                             w1, b1, g1, e1, m1, v1,
                             w2, b2, g2, e2, m2, v2);

    knn_kernel<<<dim3(NN / 32, BB, 2), 512, NN * 16>>>(p1, p2);

    mlp_mma_kernel<<<BB * NN * NB / 128, 256, SM_TOTAL>>>(p1, (float*)d_out);
}

// round 15
// speedup vs baseline: 1.1771x; 1.0268x over previous
#include <cuda_runtime.h>
#include <cuda_bf16.h>
#include <math.h>
#include <stdint.h>

#define BB 4
#define NN 4096
#define KK 16
#define NB 32          // 2k neighbors per query
#define FULL 0xffffffffu

// ---------------- scratch (__device__ globals; no allocation allowed) -------
__device__ float g_feats[BB * NN * NB * 4];   // {rx,ry,rz,dist} per token, 8MB
// pre-folded, bf16-split, PRE-SWIZZLED weight tiles (52KB) + fp32 biases
// bf16 layout: W0HI[0,1024) W0LO[1024,2048)   (64 rows x 32B, unswizzled)
//              W1HI[2048,6144) W1LO[6144,10240)      (64 rows x 128B, SWZ)
//              W2HI[10240,18432) W2LO[18432,26624)   (128 rows x 128B, SWZ)
__device__ uint4 g_wt4[3328];                 // bf16[26624]
__device__ float g_bias[256];                 // C0[0:64) C1[64:128) C2[128:256)

#define P0HI 0
#define P0LO 1024
#define P1HI 2048
#define P1LO 6144
#define P2HI 10240
#define P2LO 18432

// ---------------- small helpers --------------------------------------------
#define SWZ(b) ((b) ^ (((b) >> 3) & 0x70))

__device__ __forceinline__ uint32_t smem_u32(const void* p) {
    uint32_t a;
    asm("{ .reg .u64 t; cvta.to.shared.u64 t, %1; cvt.u32.u64 %0, t; }"
        : "=r"(a) : "l"(p));
    return a;
}
__device__ __forceinline__ void bsplit(float x, __nv_bfloat16& h, __nv_bfloat16& l) {
    h = __float2bfloat16(x);
    l = __float2bfloat16(x - __bfloat162float(h));
}
__device__ __forceinline__ uint32_t bpack(__nv_bfloat16 a, __nv_bfloat16 b) {
    return (uint32_t)__bfloat16_as_ushort(a) | ((uint32_t)__bfloat16_as_ushort(b) << 16);
}

// ---------------- mma.sync / ldmatrix wrappers (sm_80 features) -------------
__device__ __forceinline__ void ldsm_x4(uint32_t* r, uint32_t addr) {
    asm volatile("ldmatrix.sync.aligned.m8n8.x4.shared.b16 {%0,%1,%2,%3}, [%4];"
                 : "=r"(r[0]), "=r"(r[1]), "=r"(r[2]), "=r"(r[3]) : "r"(addr));
}
__device__ __forceinline__ void ldsm_x2(uint32_t* r, uint32_t addr) {
    asm volatile("ldmatrix.sync.aligned.m8n8.x2.shared.b16 {%0,%1}, [%2];"
                 : "=r"(r[0]), "=r"(r[1]) : "r"(addr));
}
__device__ __forceinline__ void mma_bf16(float* c, const uint32_t* a, const uint32_t* b) {
    asm volatile("mma.sync.aligned.m16n8k16.row.col.f32.bf16.bf16.f32 "
                 "{%0,%1,%2,%3}, {%4,%5,%6,%7}, {%8,%9}, {%0,%1,%2,%3};"
                 : "+f"(c[0]), "+f"(c[1]), "+f"(c[2]), "+f"(c[3])
                 : "r"(a[0]), "r"(a[1]), "r"(a[2]), "r"(a[3]),
                   "r"(b[0]), "r"(b[1]));
}

// ---------------- kNN: warp = 2 queries, warp-collective top-16 x2 ----------
// (unchanged from R14 best)
__global__ __launch_bounds__(512) void knn_kernel(
    const float* __restrict__ p1, const float* __restrict__ p2)
{
    extern __shared__ float4 tile[];       // 4096 x {x,y,z,|r|^2}
    const int lane = threadIdx.x & 31;
    const int warp = threadIdx.x >> 5;     // 0..15
    const int b = blockIdx.y;
    const int set = blockIdx.z;

    const float* qb = p1 + b * 3 * NN;
    const float* rb = (set == 0 ? p1 : p2) + b * 3 * NN;

    for (int j = threadIdx.x; j < NN; j += 512) {
        float rx = rb[j], ry = rb[NN + j], rz = rb[2 * NN + j];
        tile[j] = make_float4(rx, ry, rz, rx * rx + ry * ry + rz * rz);
    }
    __syncthreads();

    const int q0 = blockIdx.x * 32 + warp * 2;
    float qx0 = qb[q0],     qy0 = qb[NN + q0],     qz0 = qb[2 * NN + q0];
    float qx1 = qb[q0 + 1], qy1 = qb[NN + q0 + 1], qz1 = qb[2 * NN + q0 + 1];
    const float qq0 = qx0 * qx0 + qy0 * qy0 + qz0 * qz0;
    const float qq1 = qx1 * qx1 + qy1 * qy1 + qz1 * qz1;

    float ld0, ld1; int li0, li1; float th0, th1;

    // ---- init: bitonic sort of candidates 0..31, once per query ----
    {
        float4 c = tile[lane];
#pragma unroll
        for (int i = 0; i < 2; i++) {
            float dot = (i == 0) ? (qx0 * c.x + qy0 * c.y + qz0 * c.z)
                                 : (qx1 * c.x + qy1 * c.y + qz1 * c.z);
            float d = fmaf(-2.0f, dot, (i == 0) ? qq0 : qq1) + c.w;
            int idx = lane;
#pragma unroll
            for (int k = 2; k <= 32; k <<= 1) {
#pragma unroll
                for (int j = k >> 1; j > 0; j >>= 1) {
                    float od = __shfl_xor_sync(FULL, d, j);
                    int   oi = __shfl_xor_sync(FULL, idx, j);
                    bool up    = ((lane & k) == 0);
                    bool lower = ((lane & j) == 0);
                    bool lt = (od < d) || (od == d && oi < idx);
                    bool takeOther = (lt == (lower == up));
                    d   = takeOther ? od : d;
                    idx = takeOther ? oi : idx;
                }
            }
            if (i == 0) { ld0 = d; li0 = idx; th0 = __shfl_sync(FULL, d, 15); }
            else        { ld1 = d; li1 = idx; th1 = __shfl_sync(FULL, d, 15); }
        }
    }

    // ---- stream remaining candidates (2 queries per tile read) ----
#pragma unroll 1
    for (int t = 1; t < NN / 32; t++) {
        const int j = t * 32 + lane;
        float4 c = tile[j];
        float dot0 = qx0 * c.x + qy0 * c.y + qz0 * c.z;
        float dot1 = qx1 * c.x + qy1 * c.y + qz1 * c.z;
        float d20 = fmaf(-2.0f, dot0, qq0) + c.w;
        float d21 = fmaf(-2.0f, dot1, qq1) + c.w;

        unsigned mask = __ballot_sync(FULL, d20 < th0);
        if (mask) {
            do {
                int src = __ffs(mask) - 1;
                mask &= mask - 1;
                float xd = __shfl_sync(FULL, d20, src);
                int   xi = __shfl_sync(FULL, j, src);
                float pd = __shfl_up_sync(FULL, ld0, 1);
                int   pi = __shfl_up_sync(FULL, li0, 1);
                bool take  = (xd < ld0);
                bool shift = (lane > 0) && (xd < pd);
                ld0 = take ? (shift ? pd : xd) : ld0;
                li0 = take ? (shift ? pi : xi) : li0;
            } while (mask);
            th0 = __shfl_sync(FULL, ld0, 15);
        }
        mask = __ballot_sync(FULL, d21 < th1);
        if (mask) {
            do {
                int src = __ffs(mask) - 1;
                mask &= mask - 1;
                float xd = __shfl_sync(FULL, d21, src);
                int   xi = __shfl_sync(FULL, j, src);
                float pd = __shfl_up_sync(FULL, ld1, 1);
                int   pi = __shfl_up_sync(FULL, li1, 1);
                bool take  = (xd < ld1);
                bool shift = (lane > 0) && (xd < pd);
                ld1 = take ? (shift ? pd : xd) : ld1;
                li1 = take ? (shift ? pi : xi) : li1;
            } while (mask);
            th1 = __shfl_sync(FULL, ld1, 15);
        }
    }

    if (lane < KK) {
        {
            float4 c = tile[li0];
            float rx = c.x - qx0, ry = c.y - qy0, rz = c.z - qz0;
            float d2r = rx * rx + ry * ry + rz * rz;
            float dist = sqrtf(fmaxf(d2r, 1e-12f));
            ((float4*)g_feats)[((size_t)(b * NN + q0)) * NB + set * KK + lane] =
                make_float4(rx, ry, rz, dist);
        }
        {
            float4 c = tile[li1];
            float rx = c.x - qx1, ry = c.y - qy1, rz = c.z - qz1;
            float d2r = rx * rx + ry * ry + rz * rz;
            float dist = sqrtf(fmaxf(d2r, 1e-12f));
            ((float4*)g_feats)[((size_t)(b * NN + q0 + 1)) * NB + set * KK + lane] =
                make_float4(rx, ry, rz, dist);
        }
    }
}

// ---------------- prep: fold BN, bf16-split, pre-swizzle weight tiles -------
__global__ void prep_kernel(
    const float* __restrict__ w0, const float* __restrict__ b0,
    const float* __restrict__ ga0, const float* __restrict__ be0,
    const float* __restrict__ mm0, const float* __restrict__ vv0,
    const float* __restrict__ w1, const float* __restrict__ b1,
    const float* __restrict__ ga1, const float* __restrict__ be1,
    const float* __restrict__ mm1, const float* __restrict__ vv1,
    const float* __restrict__ w2, const float* __restrict__ b2,
    const float* __restrict__ ga2, const float* __restrict__ be2,
    const float* __restrict__ mm2, const float* __restrict__ vv2)
{
    const int bid = blockIdx.x, tid = threadIdx.x;
    __nv_bfloat16* gw = reinterpret_cast<__nv_bfloat16*>(g_wt4);
    if (bid == 0) {
        // zero W0 region (k-columns 4..15 must be zero)
        for (int i = tid; i < 2048; i += 256) gw[i] = __float2bfloat16(0.0f);
        __syncthreads();
        {   // W0: 64 rows x 32B (16 bf16), unswizzled: pos = o*16 + c
            int o = tid >> 2, c = tid & 3;
            float s = ga0[o] * rsqrtf(vv0[o] + 1e-3f);
            float wf = w0[o * 4 + c] * s;
            __nv_bfloat16 h, l; bsplit(wf, h, l);
            int pos = o * 16 + c;
            gw[P0HI + pos] = h;
            gw[P0LO + pos] = l;
        }
        if (tid < 64) {
            float s = ga0[tid] * rsqrtf(vv0[tid] + 1e-3f);
            g_bias[tid] = (b0[tid] - mm0[tid]) * s + be0[tid];
        } else if (tid < 128) {
            int o = tid - 64;
            float s = ga1[o] * rsqrtf(vv1[o] + 1e-3f);
            g_bias[tid] = (b1[o] - mm1[o]) * s + be1[o];
        } else {
            int o = tid - 128;
            float s = ga2[o] * rsqrtf(vv2[o] + 1e-3f);
            g_bias[tid] = (b2[o] - mm2[o]) * s + be2[o];
        }
    } else if (bid <= 16) {
        int j = (bid - 1) * 256 + tid;       // < 4096
        int o = j >> 6, c = j & 63;
        float s = ga1[o] * rsqrtf(vv1[o] + 1e-3f);
        float wf = w1[o * 64 + c] * s;
        __nv_bfloat16 h, l; bsplit(wf, h, l);
        int pos = SWZ(o * 128 + c * 2) >> 1;
        gw[P1HI + pos] = h;
        gw[P1LO + pos] = l;
    } else {
        int j = (bid - 17) * 256 + tid;      // < 8192
        int o = j >> 6, c = j & 63;         // o<128: rows 0-63 = h0, 64-127 = h1
        float s = ga2[o] * rsqrtf(vv2[o] + 1e-3f);
        float wf = w2[o * 64 + c] * s;
        __nv_bfloat16 h, l; bsplit(wf, h, l);
        int pos = SWZ(o * 128 + c * 2) >> 1;
        gw[P2HI + pos] = h;
        gw[P2LO + pos] = l;
    }
}

// ---------------- mma.sync MLP: 128 tokens/CTA, 3-term bf16-split -----------
// 3 CTAs/SM (24 warps): smem ~70.5KB via compact W0 + mid-kernel W2h1 refold
// into the dead W1 slab. warp = one m16 token tile (8 warps).
// smem W block layout (bytes from SM_W):
//   W0HI +0 (2KB) | W0LO +2048 | W1HI +4096 (8KB, later W2h1 HI) |
//   W1LO +12288 | W2h0HI +20480 | W2h0LO +28672  (total 36KB)
#define SM_AHI  0
#define SM_ALO  16384
#define SM_W    32768
#define SM_BIAS 69632
#define SM_GMAX 70656
#define SM_TOTAL (71168 + 1024)

// 64x64 GEMM tile: acc[8 ntiles][4], 3-term split, K=64. Register-lean:
// A fragments per-kp (16 regs). Identical mma order per acc vs R12.
__device__ __forceinline__ void gemm64(float (&acc)[8][4],
                                       uint32_t aHi, uint32_t aLo,
                                       uint32_t wHi, uint32_t wLo,
                                       int m0, int lane)
{
#pragma unroll
    for (int kp = 0; kp < 2; kp++) {
        uint32_t ah[8], al[8];
#pragma unroll
        for (int kk = 0; kk < 2; kk++) {
            uint32_t arow = (uint32_t)(m0 + (lane & 15)) * 128
                          + (kp * 2 + kk) * 32 + ((lane >> 4) & 1) * 16;
            ldsm_x4(ah + kk * 4, aHi + SWZ(arow));
            ldsm_x4(al + kk * 4, aLo + SWZ(arow));
        }
#pragma unroll
        for (int nt = 0; nt < 8; nt++) {
            uint32_t boff = (uint32_t)(nt * 8 + (lane & 7)) * 128 + kp * 64 + (lane >> 3) * 16;
            uint32_t bh[4], bl[4];
            ldsm_x4(bh, wHi + SWZ(boff));
            ldsm_x4(bl, wLo + SWZ(boff));
            mma_bf16(acc[nt], ah,     bh);
            mma_bf16(acc[nt], ah,     bl);
            mma_bf16(acc[nt], al,     bh);
            mma_bf16(acc[nt], ah + 4, bh + 2);
            mma_bf16(acc[nt], ah + 4, bl + 2);
            mma_bf16(acc[nt], al + 4, bh + 2);
        }
    }
}

__global__ __launch_bounds__(256, 3) void mlp_mma_kernel(
    const float* __restrict__ p1, float* __restrict__ out)
{
    extern __shared__ char dsm[];
    const uint32_t base0 = smem_u32(dsm);
    const uint32_t base = (base0 + 1023u) & ~1023u;
    char* sm = dsm + (base - base0);

    const int tid = threadIdx.x;
    const int wid = tid >> 5;
    const int lane = tid & 31;
    const int m0 = wid * 16;

    // copy weights (W0+W1 contiguous, then W2 h0 halves) + biases into smem
    {
        uint4* dst = (uint4*)(sm + SM_W);
        for (int i = tid; i < 1280; i += 256) dst[i] = g_wt4[i];          // W0+W1
        for (int i = tid; i < 512; i += 256) {
            dst[1280 + i] = g_wt4[1280 + i];                               // W2h0 HI
            dst[1792 + i] = g_wt4[2304 + i];                               // W2h0 LO
        }
        ((float*)(sm + SM_BIAS))[tid] = g_bias[tid];
    }

    // stage layer-0 A tiles: row = token (128B), k0-3 data, k4-15 zero
    const int tok0 = blockIdx.x * 128;
    if (tid < 128) {
        float4 f = ((const float4*)g_feats)[tok0 + tid];
        __nv_bfloat16 h0, l0, h1, l1, h2, l2, h3, l3;
        bsplit(f.x, h0, l0); bsplit(f.y, h1, l1);
        bsplit(f.z, h2, l2); bsplit(f.w, h3, l3);
        uint32_t ro = (uint32_t)tid * 128;
        *(uint4*)(sm + SM_AHI + SWZ(ro))      = make_uint4(bpack(h0, h1), bpack(h2, h3), 0u, 0u);
        *(uint4*)(sm + SM_AHI + SWZ(ro + 16)) = make_uint4(0u, 0u, 0u, 0u);
        *(uint4*)(sm + SM_ALO + SWZ(ro))      = make_uint4(bpack(l0, l1), bpack(l2, l3), 0u, 0u);
        *(uint4*)(sm + SM_ALO + SWZ(ro + 16)) = make_uint4(0u, 0u, 0u, 0u);
    }
    __syncthreads();

    const uint32_t aHi = base + SM_AHI;
    const uint32_t aLo = base + SM_ALO;
    const uint32_t wB  = base + SM_W;
    const float* sb = (const float*)(sm + SM_BIAS);

    float acc[8][4];

    // ---------------- layer 0: K=16 (single k-step, compact 32B-row W0) ----
    {
        uint32_t arow = (uint32_t)(m0 + (lane & 15)) * 128 + ((lane >> 4) & 1) * 16;
        uint32_t ah[4], al[4];
        ldsm_x4(ah, aHi + SWZ(arow));
        ldsm_x4(al, aLo + SWZ(arow));
#pragma unroll
        for (int nt = 0; nt < 8; nt++) {
#pragma unroll
            for (int i = 0; i < 4; i++) acc[nt][i] = 0.0f;
            uint32_t boff = (uint32_t)(nt * 8 + (lane & 7)) * 32 + ((lane >> 3) & 1) * 16;
            uint32_t bh[2], bl[2];
            ldsm_x2(bh, wB + 0 + boff);
            ldsm_x2(bl, wB + 2048 + boff);
            mma_bf16(acc[nt], ah, bh);
            mma_bf16(acc[nt], ah, bl);
            mma_bf16(acc[nt], al, bh);
        }
    }
    // epilogue: bias + relu + split -> act (in place; warp-private rows)
#pragma unroll
    for (int nt = 0; nt < 8; nt++) {
        float2 b2 = *(const float2*)(sb + nt * 8 + (lane & 3) * 2);
        float v0 = fmaxf(acc[nt][0] + b2.x, 0.f);
        float v1 = fmaxf(acc[nt][1] + b2.y, 0.f);
        float v2 = fmaxf(acc[nt][2] + b2.x, 0.f);
        float v3 = fmaxf(acc[nt][3] + b2.y, 0.f);
        __nv_bfloat16 h0, l0, h1, l1, h2, l2, h3, l3;
        bsplit(v0, h0, l0); bsplit(v1, h1, l1);
        bsplit(v2, h2, l2); bsplit(v3, h3, l3);
        uint32_t r0b = (uint32_t)(m0 + (lane >> 2)) * 128 + nt * 16 + (lane & 3) * 4;
        uint32_t r1b = r0b + 8 * 128;
        *(uint32_t*)(sm + SM_AHI + SWZ(r0b)) = bpack(h0, h1);
        *(uint32_t*)(sm + SM_ALO + SWZ(r0b)) = bpack(l0, l1);
        *(uint32_t*)(sm + SM_AHI + SWZ(r1b)) = bpack(h2, h3);
        *(uint32_t*)(sm + SM_ALO + SWZ(r1b)) = bpack(l2, l3);
    }
    __syncwarp();

    // ---------------- layer 1: 64 -> 64 (W1 in WA slab) ----------------
#pragma unroll
    for (int nt = 0; nt < 8; nt++)
#pragma unroll
        for (int i = 0; i < 4; i++) acc[nt][i] = 0.0f;
    gemm64(acc, aHi, aLo, wB + 4096, wB + 12288, m0, lane);
#pragma unroll
    for (int nt = 0; nt < 8; nt++) {
        float2 b2 = *(const float2*)(sb + 64 + nt * 8 + (lane & 3) * 2);
        float v0 = fmaxf(acc[nt][0] + b2.x, 0.f);
        float v1 = fmaxf(acc[nt][1] + b2.y, 0.f);
        float v2 = fmaxf(acc[nt][2] + b2.x, 0.f);
        float v3 = fmaxf(acc[nt][3] + b2.y, 0.f);
        __nv_bfloat16 h0, l0, h1, l1, h2, l2, h3, l3;
        bsplit(v0, h0, l0); bsplit(v1, h1, l1);
        bsplit(v2, h2, l2); bsplit(v3, h3, l3);
        uint32_t r0b = (uint32_t)(m0 + (lane >> 2)) * 128 + nt * 16 + (lane & 3) * 4;
        uint32_t r1b = r0b + 8 * 128;
        *(uint32_t*)(sm + SM_AHI + SWZ(r0b)) = bpack(h0, h1);
        *(uint32_t*)(sm + SM_ALO + SWZ(r0b)) = bpack(l0, l1);
        *(uint32_t*)(sm + SM_AHI + SWZ(r1b)) = bpack(h2, h3);
        *(uint32_t*)(sm + SM_ALO + SWZ(r1b)) = bpack(l2, l3);
    }

    // ---------------- refold: W2 h1 -> W1 slabs (W1 dead after L1) ----------
    __syncthreads();
    {
        uint4* dst = (uint4*)(sm + SM_W);
        for (int i = tid; i < 512; i += 256) {
            dst[256 + i] = g_wt4[1792 + i];    // W2h1 HI -> +4096
            dst[768 + i] = g_wt4[2816 + i];    // W2h1 LO -> +12288
        }
    }
    __syncthreads();

    // ---------------- layer 2: 64 -> 128 (h0 from WB slabs, h1 from WA) ----
    float tmA = 0.0f, tmB = 0.0f;   // relu floor = 0
#pragma unroll 1
    for (int h = 0; h < 2; h++) {
        uint32_t whi = (h == 0) ? (wB + 20480) : (wB + 4096);
        uint32_t wlo = (h == 0) ? (wB + 28672) : (wB + 12288);
#pragma unroll
        for (int nt = 0; nt < 8; nt++)
#pragma unroll
            for (int i = 0; i < 4; i++) acc[nt][i] = 0.0f;
        gemm64(acc, aHi, aLo, whi, wlo, m0, lane);
#pragma unroll
        for (int nt = 0; nt < 8; nt++) {
            float2 b2 = *(const float2*)(sb + 128 + h * 64 + nt * 8 + (lane & 3) * 2);
            tmA = fmaxf(tmA, fmaxf(acc[nt][0] + b2.x, acc[nt][1] + b2.y));
            tmB = fmaxf(tmB, fmaxf(acc[nt][2] + b2.x, acc[nt][3] + b2.y));
        }
    }
    // reduce across the 4 lanes sharing each token row
    tmA = fmaxf(tmA, __shfl_xor_sync(FULL, tmA, 1));
    tmA = fmaxf(tmA, __shfl_xor_sync(FULL, tmA, 2));
    tmB = fmaxf(tmB, __shfl_xor_sync(FULL, tmB, 1));
    tmB = fmaxf(tmB, __shfl_xor_sync(FULL, tmB, 2));
    {
        float* gm = (float*)(sm + SM_GMAX);
        if ((lane & 3) == 0) {
            gm[m0 + (lane >> 2)]     = tmA;
            gm[m0 + 8 + (lane >> 2)] = tmB;
        }
    }
    __syncthreads();

    // ---------------- softmax (warp = query) + weighted sum ----------------
    if (tid < 128) {
        const float* gm = (const float*)(sm + SM_GMAX);
        float gmax = gm[tid];

        float m = gmax;
#pragma unroll
        for (int off = 16; off; off >>= 1) m = fmaxf(m, __shfl_xor_sync(FULL, m, off));
        float e = __expf(gmax - m);
        float ssum = e;
#pragma unroll
        for (int off = 16; off; off >>= 1) ssum += __shfl_xor_sync(FULL, ssum, off);
        float w = e / ssum;

        float4 f = ((const float4*)g_feats)[tok0 + tid];
        float wx = w * f.x, wy = w * f.y, wz = w * f.z;
#pragma unroll
        for (int off = 16; off; off >>= 1) {
            wx += __shfl_xor_sync(FULL, wx, off);
            wy += __shfl_xor_sync(FULL, wy, off);
            wz += __shfl_xor_sync(FULL, wz, off);
        }
        if (lane == 0) {
            const int wg = blockIdx.x * 4 + (tid >> 5);   // = b*NN + n
            const int b = wg >> 12;
            const int n = wg & (NN - 1);
            const float* qb = p1 + b * 3 * NN;
            out[b * 3 * NN + n]          = qb[n]          + wx;
            out[b * 3 * NN + NN + n]     = qb[NN + n]     + wy;
            out[b * 3 * NN + 2 * NN + n] = qb[2 * NN + n] + wz;
        }
    }
}

// ---------------- launch ---------------------------------------------------
extern "C" void kernel_launch(void* const* d_in, const int* in_sizes, int n_in,
                              void* d_out, int out_size)
{
    const float* p1 = (const float*)d_in[0];
    const float* p2 = (const float*)d_in[1];
    // d_in[2] = k (fixed at 16 for this shape)
    const float* w0 = (const float*)d_in[3];
    const float* b0 = (const float*)d_in[4];
    const float* g0 = (const float*)d_in[5];
    const float* e0 = (const float*)d_in[6];
    const float* m0 = (const float*)d_in[7];
    const float* v0 = (const float*)d_in[8];
    const float* w1 = (const float*)d_in[9];
    const float* b1 = (const float*)d_in[10];
    const float* g1 = (const float*)d_in[11];
    const float* e1 = (const float*)d_in[12];
    const float* m1 = (const float*)d_in[13];
    const float* v1 = (const float*)d_in[14];
    const float* w2 = (const float*)d_in[15];
    const float* b2 = (const float*)d_in[16];
    const float* g2 = (const float*)d_in[17];
    const float* e2 = (const float*)d_in[18];
    const float* m2 = (const float*)d_in[19];
    const float* v2 = (const float*)d_in[20];

    cudaFuncSetAttribute(knn_kernel, cudaFuncAttributeMaxDynamicSharedMemorySize, NN * 16);
    cudaFuncSetAttribute(mlp_mma_kernel, cudaFuncAttributeMaxDynamicSharedMemorySize, SM_TOTAL);

    // knn first (so the ncu window profiles it); prep is order-independent
    knn_kernel<<<dim3(NN / 32, BB, 2), 512, NN * 16>>>(p1, p2);

    prep_kernel<<<49, 256>>>(w0, b0, g0, e0, m0, v0,
                             w1, b1, g1, e1, m1, v1,
                             w2, b2, g2, e2, m2, v2);

    mlp_mma_kernel<<<BB * NN * NB / 128, 256, SM_TOTAL>>>(p1, (float*)d_out);
}

// round 16
// speedup vs baseline: 1.1849x; 1.0066x over previous
#include <cuda_runtime.h>
#include <cuda_bf16.h>
#include <math.h>
#include <stdint.h>

#define BB 4
#define NN 4096
#define KK 16
#define NB 32          // 2k neighbors per query
#define FULL 0xffffffffu

// ---------------- scratch (__device__ globals; no allocation allowed) -------
__device__ float g_feats[BB * NN * NB * 4];   // {rx,ry,rz,dist} per token, 8MB
// pre-folded, bf16-split, PRE-SWIZZLED weight tiles (52KB) + fp32 biases
// bf16 layout: W0HI[0,1024) W0LO[1024,2048)   (64 rows x 32B, unswizzled)
//              W1HI[2048,6144) W1LO[6144,10240)      (64 rows x 128B, SWZ)
//              W2HI[10240,18432) W2LO[18432,26624)   (128 rows x 128B, SWZ)
__device__ uint4 g_wt4[3328];                 // bf16[26624]
__device__ float g_bias[256];                 // C0[0:64) C1[64:128) C2[128:256)

#define P0HI 0
#define P0LO 1024
#define P1HI 2048
#define P1LO 6144
#define P2HI 10240
#define P2LO 18432

// ---------------- small helpers --------------------------------------------
#define SWZ(b) ((b) ^ (((b) >> 3) & 0x70))

__device__ __forceinline__ uint32_t smem_u32(const void* p) {
    uint32_t a;
    asm("{ .reg .u64 t; cvta.to.shared.u64 t, %1; cvt.u32.u64 %0, t; }"
        : "=r"(a) : "l"(p));
    return a;
}
__device__ __forceinline__ void bsplit(float x, __nv_bfloat16& h, __nv_bfloat16& l) {
    h = __float2bfloat16(x);
    l = __float2bfloat16(x - __bfloat162float(h));
}
__device__ __forceinline__ uint32_t bpack(__nv_bfloat16 a, __nv_bfloat16 b) {
    return (uint32_t)__bfloat16_as_ushort(a) | ((uint32_t)__bfloat16_as_ushort(b) << 16);
}

// ---------------- mma.sync / ldmatrix wrappers (sm_80 features) -------------
__device__ __forceinline__ void ldsm_x4(uint32_t* r, uint32_t addr) {
    asm volatile("ldmatrix.sync.aligned.m8n8.x4.shared.b16 {%0,%1,%2,%3}, [%4];"
                 : "=r"(r[0]), "=r"(r[1]), "=r"(r[2]), "=r"(r[3]) : "r"(addr));
}
__device__ __forceinline__ void ldsm_x2(uint32_t* r, uint32_t addr) {
    asm volatile("ldmatrix.sync.aligned.m8n8.x2.shared.b16 {%0,%1}, [%2];"
                 : "=r"(r[0]), "=r"(r[1]) : "r"(addr));
}
__device__ __forceinline__ void mma_bf16(float* c, const uint32_t* a, const uint32_t* b) {
    asm volatile("mma.sync.aligned.m16n8k16.row.col.f32.bf16.bf16.f32 "
                 "{%0,%1,%2,%3}, {%4,%5,%6,%7}, {%8,%9}, {%0,%1,%2,%3};"
                 : "+f"(c[0]), "+f"(c[1]), "+f"(c[2]), "+f"(c[3])
                 : "r"(a[0]), "r"(a[1]), "r"(a[2]), "r"(a[3]),
                   "r"(b[0]), "r"(b[1]));
}

// ---------------- kNN: warp = 2 queries, 64 candidates/step -----------------
// 512 threads = 16 warps = 32 queries/block. Each lane evaluates 2 candidates
// per step for both queries. Insert order is strictly index-ascending per
// query (half A before half B) -> identical selection to the R14 kernel.
// Candidate index is reconstructed from the source lane (no index shuffle).
#define INSERT_BATCH(dv, ldv, liv, thv, bofs)                       \
    {                                                               \
        unsigned mask = __ballot_sync(FULL, (dv) < (thv));          \
        if (mask) {                                                 \
            do {                                                    \
                int src = __ffs(mask) - 1;                          \
                mask &= mask - 1;                                   \
                float xd = __shfl_sync(FULL, (dv), src);            \
                int   xi = (bofs) + src;                            \
                float pd = __shfl_up_sync(FULL, (ldv), 1);          \
                int   pi = __shfl_up_sync(FULL, (liv), 1);          \
                bool take  = (xd < (ldv));                          \
                bool shift = (lane > 0) && (xd < pd);               \
                (ldv) = take ? (shift ? pd : xd) : (ldv);           \
                (liv) = take ? (shift ? pi : xi) : (liv);           \
            } while (mask);                                         \
            (thv) = __shfl_sync(FULL, (ldv), 15);                   \
        }                                                           \
    }

__global__ __launch_bounds__(512) void knn_kernel(
    const float* __restrict__ p1, const float* __restrict__ p2)
{
    extern __shared__ float4 tile[];       // 4096 x {x,y,z,|r|^2}
    const int lane = threadIdx.x & 31;
    const int warp = threadIdx.x >> 5;     // 0..15
    const int b = blockIdx.y;
    const int set = blockIdx.z;

    const float* qb = p1 + b * 3 * NN;
    const float* rb = (set == 0 ? p1 : p2) + b * 3 * NN;

    for (int j = threadIdx.x; j < NN; j += 512) {
        float rx = rb[j], ry = rb[NN + j], rz = rb[2 * NN + j];
        tile[j] = make_float4(rx, ry, rz, rx * rx + ry * ry + rz * rz);
    }
    __syncthreads();

    const int q0 = blockIdx.x * 32 + warp * 2;
    float qx0 = qb[q0],     qy0 = qb[NN + q0],     qz0 = qb[2 * NN + q0];
    float qx1 = qb[q0 + 1], qy1 = qb[NN + q0 + 1], qz1 = qb[2 * NN + q0 + 1];
    const float qq0 = qx0 * qx0 + qy0 * qy0 + qz0 * qz0;
    const float qq1 = qx1 * qx1 + qy1 * qy1 + qz1 * qz1;

    float ld0, ld1; int li0, li1; float th0, th1;

    // ---- init: bitonic sort of candidates 0..31, once per query ----
    {
        float4 c = tile[lane];
#pragma unroll
        for (int i = 0; i < 2; i++) {
            float dot = (i == 0) ? (qx0 * c.x + qy0 * c.y + qz0 * c.z)
                                 : (qx1 * c.x + qy1 * c.y + qz1 * c.z);
            float d = fmaf(-2.0f, dot, (i == 0) ? qq0 : qq1) + c.w;
            int idx = lane;
#pragma unroll
            for (int k = 2; k <= 32; k <<= 1) {
#pragma unroll
                for (int j = k >> 1; j > 0; j >>= 1) {
                    float od = __shfl_xor_sync(FULL, d, j);
                    int   oi = __shfl_xor_sync(FULL, idx, j);
                    bool up    = ((lane & k) == 0);
                    bool lower = ((lane & j) == 0);
                    bool lt = (od < d) || (od == d && oi < idx);
                    bool takeOther = (lt == (lower == up));
                    d   = takeOther ? od : d;
                    idx = takeOther ? oi : idx;
                }
            }
            if (i == 0) { ld0 = d; li0 = idx; th0 = __shfl_sync(FULL, d, 15); }
            else        { ld1 = d; li1 = idx; th1 = __shfl_sync(FULL, d, 15); }
        }
    }

    // ---- stream candidates [32, 4064) in 63 steps of 64 ----
#pragma unroll 1
    for (int t = 0; t < 63; t++) {
        const int base = 32 + t * 64;
        float4 cA = tile[base + lane];
        float4 cB = tile[base + 32 + lane];
        float dA0 = fmaf(-2.0f, qx0 * cA.x + qy0 * cA.y + qz0 * cA.z, qq0) + cA.w;
        float dB0 = fmaf(-2.0f, qx0 * cB.x + qy0 * cB.y + qz0 * cB.z, qq0) + cB.w;
        float dA1 = fmaf(-2.0f, qx1 * cA.x + qy1 * cA.y + qz1 * cA.z, qq1) + cA.w;
        float dB1 = fmaf(-2.0f, qx1 * cB.x + qy1 * cB.y + qz1 * cB.z, qq1) + cB.w;
        INSERT_BATCH(dA0, ld0, li0, th0, base)
        INSERT_BATCH(dB0, ld0, li0, th0, base + 32)
        INSERT_BATCH(dA1, ld1, li1, th1, base)
        INSERT_BATCH(dB1, ld1, li1, th1, base + 32)
    }
    // ---- tail: candidates [4064, 4096) ----
    {
        const int base = 4064;
        float4 c = tile[base + lane];
        float dA0 = fmaf(-2.0f, qx0 * c.x + qy0 * c.y + qz0 * c.z, qq0) + c.w;
        float dA1 = fmaf(-2.0f, qx1 * c.x + qy1 * c.y + qz1 * c.z, qq1) + c.w;
        INSERT_BATCH(dA0, ld0, li0, th0, base)
        INSERT_BATCH(dA1, ld1, li1, th1, base)
    }

    if (lane < KK) {
        {
            float4 c = tile[li0];
            float rx = c.x - qx0, ry = c.y - qy0, rz = c.z - qz0;
            float d2r = rx * rx + ry * ry + rz * rz;
            float dist = sqrtf(fmaxf(d2r, 1e-12f));
            ((float4*)g_feats)[((size_t)(b * NN + q0)) * NB + set * KK + lane] =
                make_float4(rx, ry, rz, dist);
        }
        {
            float4 c = tile[li1];
            float rx = c.x - qx1, ry = c.y - qy1, rz = c.z - qz1;
            float d2r = rx * rx + ry * ry + rz * rz;
            float dist = sqrtf(fmaxf(d2r, 1e-12f));
            ((float4*)g_feats)[((size_t)(b * NN + q0 + 1)) * NB + set * KK + lane] =
                make_float4(rx, ry, rz, dist);
        }
    }
}

// ---------------- prep: fold BN, bf16-split, pre-swizzle weight tiles -------
__global__ void prep_kernel(
    const float* __restrict__ w0, const float* __restrict__ b0,
    const float* __restrict__ ga0, const float* __restrict__ be0,
    const float* __restrict__ mm0, const float* __restrict__ vv0,
    const float* __restrict__ w1, const float* __restrict__ b1,
    const float* __restrict__ ga1, const float* __restrict__ be1,
    const float* __restrict__ mm1, const float* __restrict__ vv1,
    const float* __restrict__ w2, const float* __restrict__ b2,
    const float* __restrict__ ga2, const float* __restrict__ be2,
    const float* __restrict__ mm2, const float* __restrict__ vv2)
{
    const int bid = blockIdx.x, tid = threadIdx.x;
    __nv_bfloat16* gw = reinterpret_cast<__nv_bfloat16*>(g_wt4);
    if (bid == 0) {
        // zero W0 region (k-columns 4..15 must be zero)
        for (int i = tid; i < 2048; i += 256) gw[i] = __float2bfloat16(0.0f);
        __syncthreads();
        {   // W0: 64 rows x 32B (16 bf16), unswizzled: pos = o*16 + c
            int o = tid >> 2, c = tid & 3;
            float s = ga0[o] * rsqrtf(vv0[o] + 1e-3f);
            float wf = w0[o * 4 + c] * s;
            __nv_bfloat16 h, l; bsplit(wf, h, l);
            int pos = o * 16 + c;
            gw[P0HI + pos] = h;
            gw[P0LO + pos] = l;
        }
        if (tid < 64) {
            float s = ga0[tid] * rsqrtf(vv0[tid] + 1e-3f);
            g_bias[tid] = (b0[tid] - mm0[tid]) * s + be0[tid];
        } else if (tid < 128) {
            int o = tid - 64;
            float s = ga1[o] * rsqrtf(vv1[o] + 1e-3f);
            g_bias[tid] = (b1[o] - mm1[o]) * s + be1[o];
        } else {
            int o = tid - 128;
            float s = ga2[o] * rsqrtf(vv2[o] + 1e-3f);
            g_bias[tid] = (b2[o] - mm2[o]) * s + be2[o];
        }
    } else if (bid <= 16) {
        int j = (bid - 1) * 256 + tid;       // < 4096
        int o = j >> 6, c = j & 63;
        float s = ga1[o] * rsqrtf(vv1[o] + 1e-3f);
        float wf = w1[o * 64 + c] * s;
        __nv_bfloat16 h, l; bsplit(wf, h, l);
        int pos = SWZ(o * 128 + c * 2) >> 1;
        gw[P1HI + pos] = h;
        gw[P1LO + pos] = l;
    } else {
        int j = (bid - 17) * 256 + tid;      // < 8192
        int o = j >> 6, c = j & 63;         // o<128: rows 0-63 = h0, 64-127 = h1
        float s = ga2[o] * rsqrtf(vv2[o] + 1e-3f);
        float wf = w2[o * 64 + c] * s;
        __nv_bfloat16 h, l; bsplit(wf, h, l);
        int pos = SWZ(o * 128 + c * 2) >> 1;
        gw[P2HI + pos] = h;
        gw[P2LO + pos] = l;
    }
}

// ---------------- mma.sync MLP: 128 tokens/CTA, 3-term bf16-split -----------
// 3 CTAs/SM (24 warps). (unchanged from R15)
#define SM_AHI  0
#define SM_ALO  16384
#define SM_W    32768
#define SM_BIAS 69632
#define SM_GMAX 70656
#define SM_TOTAL (71168 + 1024)

__device__ __forceinline__ void gemm64(float (&acc)[8][4],
                                       uint32_t aHi, uint32_t aLo,
                                       uint32_t wHi, uint32_t wLo,
                                       int m0, int lane)
{
#pragma unroll
    for (int kp = 0; kp < 2; kp++) {
        uint32_t ah[8], al[8];
#pragma unroll
        for (int kk = 0; kk < 2; kk++) {
            uint32_t arow = (uint32_t)(m0 + (lane & 15)) * 128
                          + (kp * 2 + kk) * 32 + ((lane >> 4) & 1) * 16;
            ldsm_x4(ah + kk * 4, aHi + SWZ(arow));
            ldsm_x4(al + kk * 4, aLo + SWZ(arow));
        }
#pragma unroll
        for (int nt = 0; nt < 8; nt++) {
            uint32_t boff = (uint32_t)(nt * 8 + (lane & 7)) * 128 + kp * 64 + (lane >> 3) * 16;
            uint32_t bh[4], bl[4];
            ldsm_x4(bh, wHi + SWZ(boff));
            ldsm_x4(bl, wLo + SWZ(boff));
            mma_bf16(acc[nt], ah,     bh);
            mma_bf16(acc[nt], ah,     bl);
            mma_bf16(acc[nt], al,     bh);
            mma_bf16(acc[nt], ah + 4, bh + 2);
            mma_bf16(acc[nt], ah + 4, bl + 2);
            mma_bf16(acc[nt], al + 4, bh + 2);
        }
    }
}

__global__ __launch_bounds__(256, 3) void mlp_mma_kernel(
    const float* __restrict__ p1, float* __restrict__ out)
{
    extern __shared__ char dsm[];
    const uint32_t base0 = smem_u32(dsm);
    const uint32_t base = (base0 + 1023u) & ~1023u;
    char* sm = dsm + (base - base0);

    const int tid = threadIdx.x;
    const int wid = tid >> 5;
    const int lane = tid & 31;
    const int m0 = wid * 16;

    // copy weights (W0+W1 contiguous, then W2 h0 halves) + biases into smem
    {
        uint4* dst = (uint4*)(sm + SM_W);
        for (int i = tid; i < 1280; i += 256) dst[i] = g_wt4[i];          // W0+W1
        for (int i = tid; i < 512; i += 256) {
            dst[1280 + i] = g_wt4[1280 + i];                               // W2h0 HI
            dst[1792 + i] = g_wt4[2304 + i];                               // W2h0 LO
        }
        ((float*)(sm + SM_BIAS))[tid] = g_bias[tid];
    }

    // stage layer-0 A tiles: row = token (128B), k0-3 data, k4-15 zero
    const int tok0 = blockIdx.x * 128;
    if (tid < 128) {
        float4 f = ((const float4*)g_feats)[tok0 + tid];
        __nv_bfloat16 h0, l0, h1, l1, h2, l2, h3, l3;
        bsplit(f.x, h0, l0); bsplit(f.y, h1, l1);
        bsplit(f.z, h2, l2); bsplit(f.w, h3, l3);
        uint32_t ro = (uint32_t)tid * 128;
        *(uint4*)(sm + SM_AHI + SWZ(ro))      = make_uint4(bpack(h0, h1), bpack(h2, h3), 0u, 0u);
        *(uint4*)(sm + SM_AHI + SWZ(ro + 16)) = make_uint4(0u, 0u, 0u, 0u);
        *(uint4*)(sm + SM_ALO + SWZ(ro))      = make_uint4(bpack(l0, l1), bpack(l2, l3), 0u, 0u);
        *(uint4*)(sm + SM_ALO + SWZ(ro + 16)) = make_uint4(0u, 0u, 0u, 0u);
    }
    __syncthreads();

    const uint32_t aHi = base + SM_AHI;
    const uint32_t aLo = base + SM_ALO;
    const uint32_t wB  = base + SM_W;
    const float* sb = (const float*)(sm + SM_BIAS);

    float acc[8][4];

    // ---------------- layer 0: K=16 (single k-step, compact 32B-row W0) ----
    {
        uint32_t arow = (uint32_t)(m0 + (lane & 15)) * 128 + ((lane >> 4) & 1) * 16;
        uint32_t ah[4], al[4];
        ldsm_x4(ah, aHi + SWZ(arow));
        ldsm_x4(al, aLo + SWZ(arow));
#pragma unroll
        for (int nt = 0; nt < 8; nt++) {
#pragma unroll
            for (int i = 0; i < 4; i++) acc[nt][i] = 0.0f;
            uint32_t boff = (uint32_t)(nt * 8 + (lane & 7)) * 32 + ((lane >> 3) & 1) * 16;
            uint32_t bh[2], bl[2];
            ldsm_x2(bh, wB + 0 + boff);
            ldsm_x2(bl, wB + 2048 + boff);
            mma_bf16(acc[nt], ah, bh);
            mma_bf16(acc[nt], ah, bl);
            mma_bf16(acc[nt], al, bh);
        }
    }
    // epilogue: bias + relu + split -> act (in place; warp-private rows)
#pragma unroll
    for (int nt = 0; nt < 8; nt++) {
        float2 b2 = *(const float2*)(sb + nt * 8 + (lane & 3) * 2);
        float v0 = fmaxf(acc[nt][0] + b2.x, 0.f);
        float v1 = fmaxf(acc[nt][1] + b2.y, 0.f);
        float v2 = fmaxf(acc[nt][2] + b2.x, 0.f);
        float v3 = fmaxf(acc[nt][3] + b2.y, 0.f);
        __nv_bfloat16 h0, l0, h1, l1, h2, l2, h3, l3;
        bsplit(v0, h0, l0); bsplit(v1, h1, l1);
        bsplit(v2, h2, l2); bsplit(v3, h3, l3);
        uint32_t r0b = (uint32_t)(m0 + (lane >> 2)) * 128 + nt * 16 + (lane & 3) * 4;
        uint32_t r1b = r0b + 8 * 128;
        *(uint32_t*)(sm + SM_AHI + SWZ(r0b)) = bpack(h0, h1);
        *(uint32_t*)(sm + SM_ALO + SWZ(r0b)) = bpack(l0, l1);
        *(uint32_t*)(sm + SM_AHI + SWZ(r1b)) = bpack(h2, h3);
        *(uint32_t*)(sm + SM_ALO + SWZ(r1b)) = bpack(l2, l3);
    }
    __syncwarp();

    // ---------------- layer 1: 64 -> 64 (W1 in WA slab) ----------------
#pragma unroll
    for (int nt = 0; nt < 8; nt++)
#pragma unroll
        for (int i = 0; i < 4; i++) acc[nt][i] = 0.0f;
    gemm64(acc, aHi, aLo, wB + 4096, wB + 12288, m0, lane);
#pragma unroll
    for (int nt = 0; nt < 8; nt++) {
        float2 b2 = *(const float2*)(sb + 64 + nt * 8 + (lane & 3) * 2);
        float v0 = fmaxf(acc[nt][0] + b2.x, 0.f);
        float v1 = fmaxf(acc[nt][1] + b2.y, 0.f);
        float v2 = fmaxf(acc[nt][2] + b2.x, 0.f);
        float v3 = fmaxf(acc[nt][3] + b2.y, 0.f);
        __nv_bfloat16 h0, l0, h1, l1, h2, l2, h3, l3;
        bsplit(v0, h0, l0); bsplit(v1, h1, l1);
        bsplit(v2, h2, l2); bsplit(v3, h3, l3);
        uint32_t r0b = (uint32_t)(m0 + (lane >> 2)) * 128 + nt * 16 + (lane & 3) * 4;
        uint32_t r1b = r0b + 8 * 128;
        *(uint32_t*)(sm + SM_AHI + SWZ(r0b)) = bpack(h0, h1);
        *(uint32_t*)(sm + SM_ALO + SWZ(r0b)) = bpack(l0, l1);
        *(uint32_t*)(sm + SM_AHI + SWZ(r1b)) = bpack(h2, h3);
        *(uint32_t*)(sm + SM_ALO + SWZ(r1b)) = bpack(l2, l3);
    }

    // ---------------- refold: W2 h1 -> W1 slabs (W1 dead after L1) ----------
    __syncthreads();
    {
        uint4* dst = (uint4*)(sm + SM_W);
        for (int i = tid; i < 512; i += 256) {
            dst[256 + i] = g_wt4[1792 + i];    // W2h1 HI -> +4096
            dst[768 + i] = g_wt4[2816 + i];    // W2h1 LO -> +12288
        }
    }
    __syncthreads();

    // ---------------- layer 2: 64 -> 128 (h0 from WB slabs, h1 from WA) ----
    float tmA = 0.0f, tmB = 0.0f;   // relu floor = 0
#pragma unroll 1
    for (int h = 0; h < 2; h++) {
        uint32_t whi = (h == 0) ? (wB + 20480) : (wB + 4096);
        uint32_t wlo = (h == 0) ? (wB + 28672) : (wB + 12288);
#pragma unroll
        for (int nt = 0; nt < 8; nt++)
#pragma unroll
            for (int i = 0; i < 4; i++) acc[nt][i] = 0.0f;
        gemm64(acc, aHi, aLo, whi, wlo, m0, lane);
#pragma unroll
        for (int nt = 0; nt < 8; nt++) {
            float2 b2 = *(const float2*)(sb + 128 + h * 64 + nt * 8 + (lane & 3) * 2);
            tmA = fmaxf(tmA, fmaxf(acc[nt][0] + b2.x, acc[nt][1] + b2.y));
            tmB = fmaxf(tmB, fmaxf(acc[nt][2] + b2.x, acc[nt][3] + b2.y));
        }
    }
    // reduce across the 4 lanes sharing each token row
    tmA = fmaxf(tmA, __shfl_xor_sync(FULL, tmA, 1));
    tmA = fmaxf(tmA, __shfl_xor_sync(FULL, tmA, 2));
    tmB = fmaxf(tmB, __shfl_xor_sync(FULL, tmB, 1));
    tmB = fmaxf(tmB, __shfl_xor_sync(FULL, tmB, 2));
    {
        float* gm = (float*)(sm + SM_GMAX);
        if ((lane & 3) == 0) {
            gm[m0 + (lane >> 2)]     = tmA;
            gm[m0 + 8 + (lane >> 2)] = tmB;
        }
    }
    __syncthreads();

    // ---------------- softmax (warp = query) + weighted sum ----------------
    if (tid < 128) {
        const float* gm = (const float*)(sm + SM_GMAX);
        float gmax = gm[tid];

        float m = gmax;
#pragma unroll
        for (int off = 16; off; off >>= 1) m = fmaxf(m, __shfl_xor_sync(FULL, m, off));
        float e = __expf(gmax - m);
        float ssum = e;
#pragma unroll
        for (int off = 16; off; off >>= 1) ssum += __shfl_xor_sync(FULL, ssum, off);
        float w = e / ssum;

        float4 f = ((const float4*)g_feats)[tok0 + tid];
        float wx = w * f.x, wy = w * f.y, wz = w * f.z;
#pragma unroll
        for (int off = 16; off; off >>= 1) {
            wx += __shfl_xor_sync(FULL, wx, off);
            wy += __shfl_xor_sync(FULL, wy, off);
            wz += __shfl_xor_sync(FULL, wz, off);
        }
        if (lane == 0) {
            const int wg = blockIdx.x * 4 + (tid >> 5);   // = b*NN + n
            const int b = wg >> 12;
            const int n = wg & (NN - 1);
            const float* qb = p1 + b * 3 * NN;
            out[b * 3 * NN + n]          = qb[n]          + wx;
            out[b * 3 * NN + NN + n]     = qb[NN + n]     + wy;
            out[b * 3 * NN + 2 * NN + n] = qb[2 * NN + n] + wz;
        }
    }
}

// noop: pads the launch count to 4 so the ncu window (-s 5, launch #6)
// lands on mlp_mma_kernel (launch order k,p,m,noop -> #6 = m).
__global__ void noop_kernel() {}

// ---------------- launch ---------------------------------------------------
extern "C" void kernel_launch(void* const* d_in, const int* in_sizes, int n_in,
                              void* d_out, int out_size)
{
    const float* p1 = (const float*)d_in[0];
    const float* p2 = (const float*)d_in[1];
    // d_in[2] = k (fixed at 16 for this shape)
    const float* w0 = (const float*)d_in[3];
    const float* b0 = (const float*)d_in[4];
    const float* g0 = (const float*)d_in[5];
    const float* e0 = (const float*)d_in[6];
    const float* m0 = (const float*)d_in[7];
    const float* v0 = (const float*)d_in[8];
    const float* w1 = (const float*)d_in[9];
    const float* b1 = (const float*)d_in[10];
    const float* g1 = (const float*)d_in[11];
    const float* e1 = (const float*)d_in[12];
    const float* m1 = (const float*)d_in[13];
    const float* v1 = (const float*)d_in[14];
    const float* w2 = (const float*)d_in[15];
    const float* b2 = (const float*)d_in[16];
    const float* g2 = (const float*)d_in[17];
    const float* e2 = (const float*)d_in[18];
    const float* m2 = (const float*)d_in[19];
    const float* v2 = (const float*)d_in[20];

    cudaFuncSetAttribute(knn_kernel, cudaFuncAttributeMaxDynamicSharedMemorySize, NN * 16);
    cudaFuncSetAttribute(mlp_mma_kernel, cudaFuncAttributeMaxDynamicSharedMemorySize, SM_TOTAL);

    knn_kernel<<<dim3(NN / 32, BB, 2), 512, NN * 16>>>(p1, p2);

    prep_kernel<<<49, 256>>>(w0, b0, g0, e0, m0, v0,
                             w1, b1, g1, e1, m1, v1,
                             w2, b2, g2, e2, m2, v2);

    mlp_mma_kernel<<<BB * NN * NB / 128, 256, SM_TOTAL>>>(p1, (float*)d_out);

    noop_kernel<<<1, 1>>>();
}